// round 14
// baseline (speedup 1.0000x reference)
#include <cuda_runtime.h>
#include <math.h>
#include <stdint.h>

// Problem constants
#define BB 2
#define SS 2048
#define DD 1024
#define HH 16
#define DHH 64
#define MM (BB*SS)          // 4096 rows
#define LAMBDA_INIT 0.8f
#define GN_EPS 1e-5f

// Scratch (device globals; no allocation allowed)
__device__ float g_Q[MM*DD];
__device__ float g_K[MM*DD];
__device__ float g_V[MM*DD];
__device__ float g_AO[MM*DD];   // attention output [B,S,H,DH]
__device__ float g_Xr[MM*DD];   // rne-tf32 rounded x
__device__ float g_Wr[4][DD*DD];// rne-tf32 rounded Wq,Wk,Wv,Wo
__device__ float g_lam[HH];
__device__ float g_mean[BB*HH];
__device__ float g_rstd[BB*HH];
__device__ double g_part[BB*HH*32*2];   // per flash tile {sum,sumsq} (1024 tiles)

// ---------------------------------------------------------------------------
// helpers
// ---------------------------------------------------------------------------
__device__ __forceinline__ float to_tf32(float x) {
    unsigned u;
    asm("cvt.rna.tf32.f32 %0, %1;" : "=r"(u) : "f"(x));
    return __uint_as_float(u);
}
__device__ __forceinline__ float ex2(float x) {
    float r;
    asm("ex2.approx.ftz.f32 %0, %1;" : "=f"(r) : "f"(x));
    return r;
}
__device__ __forceinline__ uint32_t smem_u32(const void* p) {
    uint32_t a;
    asm("{ .reg .u64 t; cvta.to.shared.u64 t, %1; cvt.u32.u64 %0, t; }" : "=r"(a) : "l"(p));
    return a;
}
__device__ __forceinline__ void cp_async16(uint32_t dst, const void* src) {
    asm volatile("cp.async.cg.shared.global [%0], [%1], 16;" :: "r"(dst), "l"(src));
}
#define CP_COMMIT() asm volatile("cp.async.commit_group;" ::: "memory")
#define CP_WAIT(n)  asm volatile("cp.async.wait_group %0;" :: "n"(n) : "memory")

__device__ __forceinline__ void mma_tf32(float* c, const float* a, const float* b) {
    const unsigned* A = reinterpret_cast<const unsigned*>(a);
    const unsigned* B = reinterpret_cast<const unsigned*>(b);
    asm volatile(
        "mma.sync.aligned.m16n8k8.row.col.f32.tf32.tf32.f32 "
        "{%0,%1,%2,%3}, {%4,%5,%6,%7}, {%8,%9}, {%0,%1,%2,%3};\n"
        : "+f"(c[0]), "+f"(c[1]), "+f"(c[2]), "+f"(c[3])
        : "r"(A[0]), "r"(A[1]), "r"(A[2]), "r"(A[3]),
          "r"(B[0]), "r"(B[1]));
}

// ---------------------------------------------------------------------------
// elementwise rne-tf32 rounding
// ---------------------------------------------------------------------------
__global__ __launch_bounds__(256) void tf32_round_kernel(const float* __restrict__ in,
                                                         float* __restrict__ out, int n4) {
    int i = blockIdx.x * 256 + threadIdx.x;
    if (i < n4) {
        float4 v = *(const float4*)(in + i * 4);
        v.x = to_tf32(v.x);
        v.y = to_tf32(v.y);
        v.z = to_tf32(v.z);
        v.w = to_tf32(v.w);
        *(float4*)(out + i * 4) = v;
    }
}

__global__ __launch_bounds__(256) void tf32_round_w4(
    const float* __restrict__ w0, const float* __restrict__ w1,
    const float* __restrict__ w2, const float* __restrict__ w3,
    float* __restrict__ out) {
    const float* in = (blockIdx.y == 0) ? w0 : (blockIdx.y == 1) ? w1
                    : (blockIdx.y == 2) ? w2 : w3;
    float* o = out + (size_t)blockIdx.y * DD * DD;
    int i = blockIdx.x * 256 + threadIdx.x;
    float4 v = *(const float4*)(in + i * 4);
    v.x = to_tf32(v.x);
    v.y = to_tf32(v.y);
    v.z = to_tf32(v.z);
    v.w = to_tf32(v.w);
    *(float4*)(o + i * 4) = v;
}

// ---------------------------------------------------------------------------
// lambda[h] = exp(<lq1,lk1>) - exp(<lq2,lk2>) + 0.8  (one warp/head)
// ---------------------------------------------------------------------------
__global__ void lambda_kernel(const float* __restrict__ lq1, const float* __restrict__ lk1,
                              const float* __restrict__ lq2, const float* __restrict__ lk2,
                              float* __restrict__ lam) {
    int h = threadIdx.x >> 5;
    int lane = threadIdx.x & 31;
    const float* a1 = lq1 + h * DHH;
    const float* b1 = lk1 + h * DHH;
    const float* a2 = lq2 + h * DHH;
    const float* b2 = lk2 + h * DHH;
    float s1 = a1[lane] * b1[lane] + a1[lane + 32] * b1[lane + 32];
    float s2 = a2[lane] * b2[lane] + a2[lane + 32] * b2[lane + 32];
    #pragma unroll
    for (int off = 16; off > 0; off >>= 1) {
        s1 += __shfl_xor_sync(0xffffffffu, s1, off);
        s2 += __shfl_xor_sync(0xffffffffu, s2, off);
    }
    if (lane == 0) lam[h] = expf(s1) - expf(s2) + LAMBDA_INIT;
}

// ---------------------------------------------------------------------------
// QKV GEMM, 128x64 tile for 3-CTA occupancy. 256 threads = 8 warps (4m x 2n),
// warp tile 32x32, BK=16, cp.async double-buffered (pre-rounded inputs).
// grid (48, 32): x 0-15 -> Q n-tiles, 16-31 -> K, 32-47 -> V.
// ---------------------------------------------------------------------------
__global__ __launch_bounds__(256, 3) void gemm_qkv64(
    const float* __restrict__ x,
    const float* __restrict__ Wq, const float* __restrict__ Wk, const float* __restrict__ Wv,
    const float* __restrict__ bq, const float* __restrict__ bk, const float* __restrict__ bv,
    float* __restrict__ Q, float* __restrict__ K, float* __restrict__ V)
{
    __shared__ float As[2][128][20];
    __shared__ float Bs[2][16][72];

    const int tid  = threadIdx.x;
    const int warp = tid >> 5;
    const int lane = tid & 31;
    const int g    = lane >> 2;
    const int tig  = lane & 3;
    const int wm   = warp >> 1;    // 0..3
    const int wn   = warp & 1;     // 0..1

    int sel = blockIdx.x >> 4;
    const float* A    = x;
    const float* B    = (sel == 0) ? Wq : (sel == 1) ? Wk : Wv;
    const float* bias = (sel == 0) ? bq : (sel == 1) ? bk : bv;
    float*       C    = (sel == 0) ? Q  : (sel == 1) ? K  : V;
    const int bn = (blockIdx.x & 15) * 64;
    const int bm = blockIdx.y * 128;

    int arow[2], akc[2];
    #pragma unroll
    for (int i = 0; i < 2; i++) {
        int idx = tid + i * 256;
        arow[i] = idx >> 2;          // 0..127
        akc[i]  = (idx & 3) << 2;    // 0,4,8,12
    }
    const int bkr = tid >> 4;          // 0..15
    const int bnc = (tid & 15) << 2;   // 0..60

    float c[2][4][4];
    #pragma unroll
    for (int mt = 0; mt < 2; mt++)
        #pragma unroll
        for (int nt = 0; nt < 4; nt++)
            #pragma unroll
            for (int r = 0; r < 4; r++) c[mt][nt][r] = 0.f;

    const int NT = DD / 16;   // 64

    auto issue_ab = [&](int kt, int buf) {
        #pragma unroll
        for (int i = 0; i < 2; i++)
            cp_async16(smem_u32(&As[buf][arow[i]][akc[i]]),
                       A + (size_t)(bm + arow[i]) * DD + kt + akc[i]);
        cp_async16(smem_u32(&Bs[buf][bkr][bnc]),
                   B + (size_t)(kt + bkr) * DD + bn + bnc);
    };

    issue_ab(0, 0);
    CP_COMMIT();

    for (int t = 0; t < NT; t++) {
        int buf = t & 1;
        if (t + 1 < NT) {
            issue_ab((t + 1) * 16, buf ^ 1);
            CP_COMMIT();
            CP_WAIT(1);
        } else {
            CP_WAIT(0);
        }
        __syncthreads();

        #pragma unroll
        for (int kk = 0; kk < 16; kk += 8) {
            float a[2][4], b[4][2];
            #pragma unroll
            for (int mt = 0; mt < 2; mt++) {
                int r0 = wm * 32 + mt * 16 + g;
                a[mt][0] = As[buf][r0][kk + tig];
                a[mt][1] = As[buf][r0 + 8][kk + tig];
                a[mt][2] = As[buf][r0][kk + tig + 4];
                a[mt][3] = As[buf][r0 + 8][kk + tig + 4];
            }
            #pragma unroll
            for (int nt = 0; nt < 4; nt++) {
                int cn = wn * 32 + nt * 8 + g;
                b[nt][0] = Bs[buf][kk + tig][cn];
                b[nt][1] = Bs[buf][kk + tig + 4][cn];
            }
            #pragma unroll
            for (int mt = 0; mt < 2; mt++)
                #pragma unroll
                for (int nt = 0; nt < 4; nt++)
                    mma_tf32(c[mt][nt], a[mt], b[nt]);
        }
        __syncthreads();
    }

    // epilogue + bias
    #pragma unroll
    for (int mt = 0; mt < 2; mt++) {
        int row = bm + wm * 32 + mt * 16 + g;
        #pragma unroll
        for (int nt = 0; nt < 4; nt++) {
            int col = bn + wn * 32 + nt * 8 + 2 * tig;
            float2 bb = *(const float2*)(bias + col);
            *(float2*)(C + (size_t)row * DD + col) =
                make_float2(c[mt][nt][0] + bb.x, c[mt][nt][1] + bb.y);
            *(float2*)(C + (size_t)(row + 8) * DD + col) =
                make_float2(c[mt][nt][2] + bb.x, c[mt][nt][3] + bb.y);
        }
    }
}

// ---------------------------------------------------------------------------
// O-projection GEMM (proven 128x128 core): A via registers with GroupNorm
// transform + rne tf32; B via cp.async (pre-rounded).
// ---------------------------------------------------------------------------
__global__ __launch_bounds__(256, 2) void gemm_o(
    const float* __restrict__ AO, const float* __restrict__ Wo,
    const float* __restrict__ bo, float* __restrict__ y,
    const float* __restrict__ mean, const float* __restrict__ rstd,
    const float* __restrict__ gnw, const float* __restrict__ gnb)
{
    __shared__ float As[2][128][20];
    __shared__ float Bs[2][16][136];

    const int tid  = threadIdx.x;
    const int warp = tid >> 5;
    const int lane = tid & 31;
    const int g    = lane >> 2;
    const int tig  = lane & 3;
    const int wm   = warp >> 2;    // 0..1
    const int wn   = warp & 3;     // 0..3
    const int bm   = blockIdx.y * 128;
    const int bn   = blockIdx.x * 128;

    int arow[2], akc[2], bkr[2], bnc[2];
    #pragma unroll
    for (int i = 0; i < 2; i++) {
        int idx = tid + i * 256;
        arow[i] = idx >> 2;
        akc[i]  = (idx & 3) << 2;
        bkr[i]  = idx >> 5;
        bnc[i]  = (idx & 31) << 2;
    }

    float c[4][4][4];
    #pragma unroll
    for (int mt = 0; mt < 4; mt++)
        #pragma unroll
        for (int nt = 0; nt < 4; nt++)
            #pragma unroll
            for (int r = 0; r < 4; r++) c[mt][nt][r] = 0.f;

    const int NT = DD / 16;
    float4 fa[2];

    auto issue_b = [&](int kt, int buf) {
        #pragma unroll
        for (int i = 0; i < 2; i++)
            cp_async16(smem_u32(&Bs[buf][bkr[i]][bnc[i]]),
                       Wo + (size_t)(kt + bkr[i]) * DD + bn + bnc[i]);
    };
    auto fetch_a = [&](int kt) {
        #pragma unroll
        for (int i = 0; i < 2; i++) {
            fa[i] = *(const float4*)(AO + (size_t)(bm + arow[i]) * DD + kt + akc[i]);
            int bi = (bm + arow[i]) >> 11;
            int k  = kt + akc[i];
            int hh = k >> 6;
            float mu = mean[bi * HH + hh];
            float rs = rstd[bi * HH + hh];
            float4 w  = *(const float4*)(gnw + k);
            float4 gb = *(const float4*)(gnb + k);
            fa[i].x = (fa[i].x - mu) * rs * w.x + gb.x;
            fa[i].y = (fa[i].y - mu) * rs * w.y + gb.y;
            fa[i].z = (fa[i].z - mu) * rs * w.z + gb.z;
            fa[i].w = (fa[i].w - mu) * rs * w.w + gb.w;
        }
    };
    auto store_a = [&](int buf) {
        #pragma unroll
        for (int i = 0; i < 2; i++) {
            As[buf][arow[i]][akc[i] + 0] = to_tf32(fa[i].x);
            As[buf][arow[i]][akc[i] + 1] = to_tf32(fa[i].y);
            As[buf][arow[i]][akc[i] + 2] = to_tf32(fa[i].z);
            As[buf][arow[i]][akc[i] + 3] = to_tf32(fa[i].w);
        }
    };

    issue_b(0, 0);
    CP_COMMIT();
    fetch_a(0);
    store_a(0);

    for (int t = 0; t < NT; t++) {
        int buf = t & 1;
        if (t + 1 < NT) {
            issue_b((t + 1) * 16, buf ^ 1);
            CP_COMMIT();
            fetch_a((t + 1) * 16);
            CP_WAIT(1);
        } else {
            CP_WAIT(0);
        }
        __syncthreads();

        #pragma unroll
        for (int kk = 0; kk < 16; kk += 8) {
            float a[4][4], b[4][2];
            #pragma unroll
            for (int mt = 0; mt < 4; mt++) {
                int r0 = wm * 64 + mt * 16 + g;
                a[mt][0] = As[buf][r0][kk + tig];
                a[mt][1] = As[buf][r0 + 8][kk + tig];
                a[mt][2] = As[buf][r0][kk + tig + 4];
                a[mt][3] = As[buf][r0 + 8][kk + tig + 4];
            }
            #pragma unroll
            for (int nt = 0; nt < 4; nt++) {
                int cn = wn * 32 + nt * 8 + g;
                b[nt][0] = Bs[buf][kk + tig][cn];
                b[nt][1] = Bs[buf][kk + tig + 4][cn];
            }
            #pragma unroll
            for (int mt = 0; mt < 4; mt++)
                #pragma unroll
                for (int nt = 0; nt < 4; nt++)
                    mma_tf32(c[mt][nt], a[mt], b[nt]);
        }

        if (t + 1 < NT) store_a(buf ^ 1);
        __syncthreads();
    }

    #pragma unroll
    for (int mt = 0; mt < 4; mt++) {
        int row = bm + wm * 64 + mt * 16 + g;
        #pragma unroll
        for (int nt = 0; nt < 4; nt++) {
            int col = bn + wn * 32 + nt * 8 + 2 * tig;
            float2 bb = *(const float2*)(bo + col);
            *(float2*)(y + (size_t)row * DD + col) =
                make_float2(c[mt][nt][0] + bb.x, c[mt][nt][1] + bb.y);
            *(float2*)(y + (size_t)(row + 8) * DD + col) =
                make_float2(c[mt][nt][2] + bb.x, c[mt][nt][3] + bb.y);
        }
    }
}

// ---------------------------------------------------------------------------
// tf32 flash attention — round-12 proven config: Br=Bc=64, 128 threads,
// 4 warps, occ 4, 1024 CTAs (one tile each), cp.async phase-pipelined K/V,
// GN partial stats fused into epilogue.
// ---------------------------------------------------------------------------
#define FLASH_TILES (BB * HH * (SS / 64))   // 1024
#define NJ (SS / 64)                        // 32
#define FLASH_SMEM ((64*68 + 64*72 + 64*68) * 4)   // Ks, Vs, Ps = 53248 B

__global__ __launch_bounds__(128, 4) void flash_tf32(
    const float* __restrict__ Q, const float* __restrict__ K,
    const float* __restrict__ V, const float* __restrict__ lam,
    float* __restrict__ O, double* __restrict__ part)
{
    extern __shared__ float smf[];
    float (*Ks)[68] = (float(*)[68])(smf);
    float (*Vs)[72] = (float(*)[72])(smf + 64 * 68);
    float (*Ps)[68] = (float(*)[68])(smf + 64 * 68 + 64 * 72);

    const int tid  = threadIdx.x;
    const int warp = tid >> 5;
    const int lane = tid & 31;
    const int g    = lane >> 2;
    const int tig  = lane & 3;
    const int r_q  = (warp << 4) + g;

    const uint32_t ks_base = smem_u32(&Ks[0][0]);
    const uint32_t vs_base = smem_u32(&Vs[0][0]);

    int fr[8], fd[8];
    #pragma unroll
    for (int i = 0; i < 8; i++) {
        int idx = tid + i * 128;
        fr[i] = idx >> 4;
        fd[i] = (idx & 15) << 2;
    }

    const int tile = blockIdx.x;
    const int bh = tile >> 5;
    const int it = tile & 31;
    const int b  = bh >> 4;
    const int h  = bh & 15;
    const int i0 = it << 6;
    const float fac = 0.125f * lam[h] * 1.4426950408889634f;

    const float* kp0 = K + (size_t)b * SS * DD + h * DHH;
    const float* vp0 = V + (size_t)b * SS * DD + h * DHH;

    #pragma unroll
    for (int i = 0; i < 8; i++)
        cp_async16(ks_base + (uint32_t)(fr[i] * 68 + fd[i]) * 4,
                   kp0 + (size_t)fr[i] * DD + fd[i]);
    CP_COMMIT();
    #pragma unroll
    for (int i = 0; i < 8; i++)
        cp_async16(vs_base + (uint32_t)(fr[i] * 72 + fd[i]) * 4,
                   vp0 + (size_t)fr[i] * DD + fd[i]);
    CP_COMMIT();

    float q[8][4];
    {
        const float* qp = Q + (size_t)(b * SS + i0 + r_q) * DD + h * DHH;
        #pragma unroll
        for (int kt = 0; kt < 8; kt++) {
            q[kt][0] = to_tf32(qp[kt * 8 + tig] * fac);
            q[kt][1] = to_tf32(qp[8 * DD + kt * 8 + tig] * fac);
            q[kt][2] = to_tf32(qp[kt * 8 + tig + 4] * fac);
            q[kt][3] = to_tf32(qp[8 * DD + kt * 8 + tig + 4] * fac);
        }
    }

    float o[8][4];
    #pragma unroll
    for (int nt = 0; nt < 8; nt++)
        #pragma unroll
        for (int r = 0; r < 4; r++) o[nt][r] = 0.f;
    float m0 = -INFINITY, m1 = -INFINITY, l0 = 0.f, l1 = 0.f;

    for (int jt = 0; jt < NJ; jt++) {
        if (jt == NJ - 1) { CP_WAIT(0); } else { CP_WAIT(1); }
        __syncthreads();

        float s[8][4];
        #pragma unroll
        for (int nt = 0; nt < 8; nt++)
            #pragma unroll
            for (int r = 0; r < 4; r++) s[nt][r] = 0.f;

        #pragma unroll
        for (int kk = 0; kk < 8; kk++) {
            #pragma unroll
            for (int nt = 0; nt < 8; nt++) {
                float bfr[2];
                bfr[0] = Ks[nt * 8 + g][kk * 8 + tig];
                bfr[1] = Ks[nt * 8 + g][kk * 8 + tig + 4];
                mma_tf32(s[nt], q[kk], bfr);
            }
        }
        __syncthreads();

        if (jt + 1 < NJ) {
            const float* kp = kp0 + (size_t)(jt + 1) * 64 * DD;
            #pragma unroll
            for (int i = 0; i < 8; i++)
                cp_async16(ks_base + (uint32_t)(fr[i] * 68 + fd[i]) * 4,
                           kp + (size_t)fr[i] * DD + fd[i]);
            CP_COMMIT();
        }

        float mx0 = -INFINITY, mx1 = -INFINITY;
        #pragma unroll
        for (int nt = 0; nt < 8; nt++) {
            mx0 = fmaxf(mx0, fmaxf(s[nt][0], s[nt][1]));
            mx1 = fmaxf(mx1, fmaxf(s[nt][2], s[nt][3]));
        }
        mx0 = fmaxf(mx0, __shfl_xor_sync(0xffffffffu, mx0, 1));
        mx0 = fmaxf(mx0, __shfl_xor_sync(0xffffffffu, mx0, 2));
        mx1 = fmaxf(mx1, __shfl_xor_sync(0xffffffffu, mx1, 1));
        mx1 = fmaxf(mx1, __shfl_xor_sync(0xffffffffu, mx1, 2));

        float mn0 = fmaxf(m0, mx0);
        float mn1 = fmaxf(m1, mx1);
        float al0 = ex2(m0 - mn0);
        float al1 = ex2(m1 - mn1);
        float lt0 = 0.f, lt1 = 0.f;
        #pragma unroll
        for (int nt = 0; nt < 8; nt++) {
            s[nt][0] = ex2(s[nt][0] - mn0); lt0 += s[nt][0];
            s[nt][1] = ex2(s[nt][1] - mn0); lt0 += s[nt][1];
            s[nt][2] = ex2(s[nt][2] - mn1); lt1 += s[nt][2];
            s[nt][3] = ex2(s[nt][3] - mn1); lt1 += s[nt][3];
        }
        lt0 += __shfl_xor_sync(0xffffffffu, lt0, 1);
        lt0 += __shfl_xor_sync(0xffffffffu, lt0, 2);
        lt1 += __shfl_xor_sync(0xffffffffu, lt1, 1);
        lt1 += __shfl_xor_sync(0xffffffffu, lt1, 2);
        l0 = l0 * al0 + lt0;
        l1 = l1 * al1 + lt1;
        m0 = mn0;
        m1 = mn1;
        #pragma unroll
        for (int nt = 0; nt < 8; nt++) {
            o[nt][0] *= al0; o[nt][1] *= al0;
            o[nt][2] *= al1; o[nt][3] *= al1;
        }

        #pragma unroll
        for (int nt = 0; nt < 8; nt++) {
            Ps[r_q][nt * 8 + 2 * tig]         = to_tf32(s[nt][0]);
            Ps[r_q][nt * 8 + 2 * tig + 1]     = to_tf32(s[nt][1]);
            Ps[r_q + 8][nt * 8 + 2 * tig]     = to_tf32(s[nt][2]);
            Ps[r_q + 8][nt * 8 + 2 * tig + 1] = to_tf32(s[nt][3]);
        }
        __syncwarp();

        if (jt == NJ - 1) { CP_WAIT(0); } else { CP_WAIT(1); }
        __syncthreads();

        #pragma unroll
        for (int kk = 0; kk < 64; kk += 8) {
            float a[4];
            a[0] = Ps[r_q][kk + tig];
            a[1] = Ps[r_q + 8][kk + tig];
            a[2] = Ps[r_q][kk + tig + 4];
            a[3] = Ps[r_q + 8][kk + tig + 4];
            #pragma unroll
            for (int nt = 0; nt < 8; nt++) {
                float bfr[2];
                bfr[0] = Vs[kk + tig][nt * 8 + g];
                bfr[1] = Vs[kk + tig + 4][nt * 8 + g];
                mma_tf32(o[nt], a, bfr);
            }
        }
        __syncthreads();

        if (jt + 1 < NJ) {
            const float* vp = vp0 + (size_t)(jt + 1) * 64 * DD;
            #pragma unroll
            for (int i = 0; i < 8; i++)
                cp_async16(vs_base + (uint32_t)(fr[i] * 72 + fd[i]) * 4,
                           vp + (size_t)fr[i] * DD + fd[i]);
            CP_COMMIT();
        }
    }

    // epilogue: write O + fused GN partial stats
    float inv0 = 1.f / l0;
    float inv1 = 1.f / l1;
    float psum = 0.f, psq = 0.f;
    float* op0 = O + (size_t)(b * SS + i0 + r_q) * DD + h * DHH;
    float* op1 = op0 + 8 * DD;
    #pragma unroll
    for (int nt = 0; nt < 8; nt++) {
        float v0 = o[nt][0] * inv0, v1 = o[nt][1] * inv0;
        float v2 = o[nt][2] * inv1, v3 = o[nt][3] * inv1;
        *(float2*)(op0 + nt * 8 + 2 * tig) = make_float2(v0, v1);
        *(float2*)(op1 + nt * 8 + 2 * tig) = make_float2(v2, v3);
        psum += v0 + v1 + v2 + v3;
        psq  += v0 * v0 + v1 * v1 + v2 * v2 + v3 * v3;
    }
    double ds = (double)psum, dq = (double)psq;
    #pragma unroll
    for (int off = 16; off > 0; off >>= 1) {
        ds += __shfl_xor_sync(0xffffffffu, ds, off);
        dq += __shfl_xor_sync(0xffffffffu, dq, off);
    }
    __shared__ double wsum[4], wsq[4];
    if (lane == 0) { wsum[warp] = ds; wsq[warp] = dq; }
    __syncthreads();
    if (tid == 0) {
        double ts = wsum[0] + wsum[1] + wsum[2] + wsum[3];
        double tq = wsq[0] + wsq[1] + wsq[2] + wsq[3];
        part[tile * 2 + 0] = ts;
        part[tile * 2 + 1] = tq;
    }
}

// ---------------------------------------------------------------------------
// GN stats final: one block, 1024 threads; warp w reduces the 32 tile-partials
// of bh = w.
// ---------------------------------------------------------------------------
__global__ __launch_bounds__(1024) void gn_stats_final(const double* __restrict__ part,
                                                       float* __restrict__ mean,
                                                       float* __restrict__ rstd)
{
    int bh   = threadIdx.x >> 5;   // 0..31
    int lane = threadIdx.x & 31;
    double s = part[(bh * 32 + lane) * 2 + 0];
    double q = part[(bh * 32 + lane) * 2 + 1];
    #pragma unroll
    for (int off = 16; off > 0; off >>= 1) {
        s += __shfl_xor_sync(0xffffffffu, s, off);
        q += __shfl_xor_sync(0xffffffffu, q, off);
    }
    if (lane == 0) {
        double n = (double)SS * DHH;
        double mu = s / n;
        double var = q / n - mu * mu;
        mean[bh] = (float)mu;
        rstd[bh] = (float)(1.0 / sqrt(var + (double)GN_EPS));
    }
}

// ---------------------------------------------------------------------------
extern "C" void kernel_launch(void* const* d_in, const int* in_sizes, int n_in,
                              void* d_out, int out_size) {
    const float* x   = (const float*)d_in[0];
    const float* Wq  = (const float*)d_in[1];
    const float* bq  = (const float*)d_in[2];
    const float* Wk  = (const float*)d_in[3];
    const float* bk  = (const float*)d_in[4];
    const float* Wv  = (const float*)d_in[5];
    const float* bv  = (const float*)d_in[6];
    const float* Wo  = (const float*)d_in[7];
    const float* bo  = (const float*)d_in[8];
    const float* lq1 = (const float*)d_in[9];
    const float* lk1 = (const float*)d_in[10];
    const float* lq2 = (const float*)d_in[11];
    const float* lk2 = (const float*)d_in[12];
    const float* gnw = (const float*)d_in[13];
    const float* gnb = (const float*)d_in[14];
    float* y = (float*)d_out;

    float *Qp, *Kp, *Vp, *AOp, *Xrp, *Wrp, *lamp, *meanp, *rstdp;
    double* partp;
    cudaGetSymbolAddress((void**)&Qp,    g_Q);
    cudaGetSymbolAddress((void**)&Kp,    g_K);
    cudaGetSymbolAddress((void**)&Vp,    g_V);
    cudaGetSymbolAddress((void**)&AOp,   g_AO);
    cudaGetSymbolAddress((void**)&Xrp,   g_Xr);
    cudaGetSymbolAddress((void**)&Wrp,   g_Wr);
    cudaGetSymbolAddress((void**)&lamp,  g_lam);
    cudaGetSymbolAddress((void**)&meanp, g_mean);
    cudaGetSymbolAddress((void**)&rstdp, g_rstd);
    cudaGetSymbolAddress((void**)&partp, g_part);

    float* Wrq = Wrp;
    float* Wrk = Wrp + (size_t)DD * DD;
    float* Wrv = Wrp + (size_t)2 * DD * DD;
    float* Wro = Wrp + (size_t)3 * DD * DD;

    static int attr_set = 0;
    if (!attr_set) {
        cudaFuncSetAttribute(flash_tf32, cudaFuncAttributeMaxDynamicSharedMemorySize,
                             FLASH_SMEM);
        attr_set = 1;
    }

    // pre-round operands to rne tf32
    tf32_round_kernel<<<(MM * DD / 4) / 256, 256>>>(x, Xrp, MM * DD / 4);
    tf32_round_w4<<<dim3((DD * DD / 4) / 256, 4), 256>>>(Wq, Wk, Wv, Wo, Wrp);

    lambda_kernel<<<1, HH * 32>>>(lq1, lk1, lq2, lk2, lamp);

    gemm_qkv64<<<dim3(48, 32), 256>>>(Xrp, Wrq, Wrk, Wrv, bq, bk, bv, Qp, Kp, Vp);

    flash_tf32<<<FLASH_TILES, 128, FLASH_SMEM>>>(Qp, Kp, Vp, lamp, AOp, partp);

    gn_stats_final<<<1, 1024>>>(partp, meanp, rstdp);

    gemm_o<<<dim3(8, 32), 256>>>(AOp, Wro, bo, y, meanp, rstdp, gnw, gnb);
}

// round 15
// speedup vs baseline: 1.0497x; 1.0497x over previous
#include <cuda_runtime.h>
#include <math.h>
#include <stdint.h>

// Problem constants
#define BB 2
#define SS 2048
#define DD 1024
#define HH 16
#define DHH 64
#define MM (BB*SS)          // 4096 rows
#define LAMBDA_INIT 0.8f
#define GN_EPS 1e-5f

// Scratch (device globals; no allocation allowed)
__device__ float g_Q[MM*DD];
__device__ float g_K[MM*DD];
__device__ float g_V[MM*DD];
__device__ float g_AO[MM*DD];   // attention output [B,S,H,DH]
__device__ float g_Xr[MM*DD];   // rne-tf32 rounded x
__device__ float g_Wr[4][DD*DD];// rne-tf32 rounded Wq,Wk,Wv,Wo
__device__ float g_lam[HH];
__device__ float g_mean[BB*HH];
__device__ float g_rstd[BB*HH];
__device__ double g_part[BB*HH*32*2];   // per flash tile {sum,sumsq} (1024 tiles)

// ---------------------------------------------------------------------------
// helpers
// ---------------------------------------------------------------------------
__device__ __forceinline__ float to_tf32(float x) {
    unsigned u;
    asm("cvt.rna.tf32.f32 %0, %1;" : "=r"(u) : "f"(x));
    return __uint_as_float(u);
}
__device__ __forceinline__ float ex2(float x) {
    float r;
    asm("ex2.approx.ftz.f32 %0, %1;" : "=f"(r) : "f"(x));
    return r;
}
__device__ __forceinline__ uint32_t smem_u32(const void* p) {
    uint32_t a;
    asm("{ .reg .u64 t; cvta.to.shared.u64 t, %1; cvt.u32.u64 %0, t; }" : "=r"(a) : "l"(p));
    return a;
}
__device__ __forceinline__ void cp_async16(uint32_t dst, const void* src) {
    asm volatile("cp.async.cg.shared.global [%0], [%1], 16;" :: "r"(dst), "l"(src));
}
#define CP_COMMIT() asm volatile("cp.async.commit_group;" ::: "memory")
#define CP_WAIT(n)  asm volatile("cp.async.wait_group %0;" :: "n"(n) : "memory")

__device__ __forceinline__ void mma_tf32(float* c, const float* a, const float* b) {
    const unsigned* A = reinterpret_cast<const unsigned*>(a);
    const unsigned* B = reinterpret_cast<const unsigned*>(b);
    asm volatile(
        "mma.sync.aligned.m16n8k8.row.col.f32.tf32.tf32.f32 "
        "{%0,%1,%2,%3}, {%4,%5,%6,%7}, {%8,%9}, {%0,%1,%2,%3};\n"
        : "+f"(c[0]), "+f"(c[1]), "+f"(c[2]), "+f"(c[3])
        : "r"(A[0]), "r"(A[1]), "r"(A[2]), "r"(A[3]),
          "r"(B[0]), "r"(B[1]));
}

// ---------------------------------------------------------------------------
// merged rne-tf32 rounding: one launch covers x (1M float4) + 4 weights
// (4 x 256K float4). Linear float4 index i: i < 2^20 -> x; else weights.
// ---------------------------------------------------------------------------
__global__ __launch_bounds__(256) void tf32_round_all(
    const float* __restrict__ x, float* __restrict__ xr,
    const float* __restrict__ w0, const float* __restrict__ w1,
    const float* __restrict__ w2, const float* __restrict__ w3,
    float* __restrict__ wr)
{
    int i = blockIdx.x * 256 + threadIdx.x;   // 0 .. 2M-1 float4s
    const float* in;
    float* out;
    if (i < (MM * DD / 4)) {                  // 1M float4s of x
        in = x + (size_t)i * 4;
        out = xr + (size_t)i * 4;
    } else {
        int j = i - (MM * DD / 4);
        int w = j >> 18;                      // 262144 float4s per weight
        int k = j & 0x3FFFF;
        const float* ws = (w == 0) ? w0 : (w == 1) ? w1 : (w == 2) ? w2 : w3;
        in = ws + (size_t)k * 4;
        out = wr + (size_t)w * DD * DD + (size_t)k * 4;
    }
    float4 v = *(const float4*)in;
    v.x = to_tf32(v.x);
    v.y = to_tf32(v.y);
    v.z = to_tf32(v.z);
    v.w = to_tf32(v.w);
    *(float4*)out = v;
}

// ---------------------------------------------------------------------------
// lambda[h] = exp(<lq1,lk1>) - exp(<lq2,lk2>) + 0.8  (one warp/head)
// ---------------------------------------------------------------------------
__global__ void lambda_kernel(const float* __restrict__ lq1, const float* __restrict__ lk1,
                              const float* __restrict__ lq2, const float* __restrict__ lk2,
                              float* __restrict__ lam) {
    int h = threadIdx.x >> 5;
    int lane = threadIdx.x & 31;
    const float* a1 = lq1 + h * DHH;
    const float* b1 = lk1 + h * DHH;
    const float* a2 = lq2 + h * DHH;
    const float* b2 = lk2 + h * DHH;
    float s1 = a1[lane] * b1[lane] + a1[lane + 32] * b1[lane + 32];
    float s2 = a2[lane] * b2[lane] + a2[lane + 32] * b2[lane + 32];
    #pragma unroll
    for (int off = 16; off > 0; off >>= 1) {
        s1 += __shfl_xor_sync(0xffffffffu, s1, off);
        s2 += __shfl_xor_sync(0xffffffffu, s2, off);
    }
    if (lane == 0) lam[h] = expf(s1) - expf(s2) + LAMBDA_INIT;
}

// ---------------------------------------------------------------------------
// tf32 tensor-core GEMM core with cp.async operand staging (round-12 proven).
// BM=128 BN=128 BK=16, 256 threads = 8 warps (2x4), warp tile 64x32.
// FUSE=0: A and B both via cp.async (inputs PRE-ROUNDED rne tf32).
// FUSE=1: A via registers with GroupNorm transform + rne tf32; B via cp.async.
// ---------------------------------------------------------------------------
template<int FUSE>
__device__ __forceinline__ void gemm_core(
    float (*As)[128][20], float (*Bs)[16][136],
    const float* __restrict__ A, const float* __restrict__ B,
    const float* __restrict__ bias, float* __restrict__ C,
    int bm, int bn,
    const float* __restrict__ mean, const float* __restrict__ rstd,
    const float* __restrict__ gnw, const float* __restrict__ gnb)
{
    const int tid  = threadIdx.x;
    const int warp = tid >> 5;
    const int lane = tid & 31;
    const int g    = lane >> 2;
    const int tig  = lane & 3;
    const int wm   = warp >> 2;    // 0..1
    const int wn   = warp & 3;     // 0..3

    int arow[2], akc[2], bkr[2], bnc[2];
    #pragma unroll
    for (int i = 0; i < 2; i++) {
        int idx = tid + i * 256;
        arow[i] = idx >> 2;          // 0..127
        akc[i]  = (idx & 3) << 2;    // 0,4,8,12
        bkr[i]  = idx >> 5;          // 0..15
        bnc[i]  = (idx & 31) << 2;   // 0..124
    }

    float c[4][4][4];
    #pragma unroll
    for (int mt = 0; mt < 4; mt++)
        #pragma unroll
        for (int nt = 0; nt < 4; nt++)
            #pragma unroll
            for (int r = 0; r < 4; r++) c[mt][nt][r] = 0.f;

    const int NT = DD / 16;
    float4 fa[2];   // FUSE=1 A staging only

    auto issue_b = [&](int kt, int buf) {
        #pragma unroll
        for (int i = 0; i < 2; i++)
            cp_async16(smem_u32(&Bs[buf][bkr[i]][bnc[i]]),
                       B + (size_t)(kt + bkr[i]) * DD + bn + bnc[i]);
    };
    auto issue_a = [&](int kt, int buf) {
        #pragma unroll
        for (int i = 0; i < 2; i++)
            cp_async16(smem_u32(&As[buf][arow[i]][akc[i]]),
                       A + (size_t)(bm + arow[i]) * DD + kt + akc[i]);
    };
    auto fetch_a = [&](int kt) {
        #pragma unroll
        for (int i = 0; i < 2; i++) {
            fa[i] = *(const float4*)(A + (size_t)(bm + arow[i]) * DD + kt + akc[i]);
            int bi = (bm + arow[i]) >> 11;
            int k  = kt + akc[i];
            int hh = k >> 6;
            float mu = mean[bi * HH + hh];
            float rs = rstd[bi * HH + hh];
            float4 w  = *(const float4*)(gnw + k);
            float4 gb = *(const float4*)(gnb + k);
            fa[i].x = (fa[i].x - mu) * rs * w.x + gb.x;
            fa[i].y = (fa[i].y - mu) * rs * w.y + gb.y;
            fa[i].z = (fa[i].z - mu) * rs * w.z + gb.z;
            fa[i].w = (fa[i].w - mu) * rs * w.w + gb.w;
        }
    };
    auto store_a = [&](int buf) {
        #pragma unroll
        for (int i = 0; i < 2; i++) {
            As[buf][arow[i]][akc[i] + 0] = to_tf32(fa[i].x);
            As[buf][arow[i]][akc[i] + 1] = to_tf32(fa[i].y);
            As[buf][arow[i]][akc[i] + 2] = to_tf32(fa[i].z);
            As[buf][arow[i]][akc[i] + 3] = to_tf32(fa[i].w);
        }
    };

    // prologue: stage tile 0
    if (FUSE) {
        issue_b(0, 0);
        CP_COMMIT();
        fetch_a(0);
        store_a(0);
    } else {
        issue_a(0, 0);
        issue_b(0, 0);
        CP_COMMIT();
    }

    for (int t = 0; t < NT; t++) {
        int buf = t & 1;
        if (t + 1 < NT) {
            if (FUSE) {
                issue_b((t + 1) * 16, buf ^ 1);
                CP_COMMIT();
                fetch_a((t + 1) * 16);
            } else {
                issue_a((t + 1) * 16, buf ^ 1);
                issue_b((t + 1) * 16, buf ^ 1);
                CP_COMMIT();
            }
            CP_WAIT(1);
        } else {
            CP_WAIT(0);
        }
        __syncthreads();

        #pragma unroll
        for (int kk = 0; kk < 16; kk += 8) {
            float a[4][4], b[4][2];
            #pragma unroll
            for (int mt = 0; mt < 4; mt++) {
                int r0 = wm * 64 + mt * 16 + g;
                a[mt][0] = As[buf][r0][kk + tig];
                a[mt][1] = As[buf][r0 + 8][kk + tig];
                a[mt][2] = As[buf][r0][kk + tig + 4];
                a[mt][3] = As[buf][r0 + 8][kk + tig + 4];
            }
            #pragma unroll
            for (int nt = 0; nt < 4; nt++) {
                int cn = wn * 32 + nt * 8 + g;
                b[nt][0] = Bs[buf][kk + tig][cn];
                b[nt][1] = Bs[buf][kk + tig + 4][cn];
            }
            #pragma unroll
            for (int mt = 0; mt < 4; mt++)
                #pragma unroll
                for (int nt = 0; nt < 4; nt++)
                    mma_tf32(c[mt][nt], a[mt], b[nt]);
        }

        if (FUSE && t + 1 < NT) store_a(buf ^ 1);
        __syncthreads();
    }

    // epilogue + bias
    #pragma unroll
    for (int mt = 0; mt < 4; mt++) {
        int row = bm + wm * 64 + mt * 16 + g;
        #pragma unroll
        for (int nt = 0; nt < 4; nt++) {
            int col = bn + wn * 32 + nt * 8 + 2 * tig;
            float2 bb = *(const float2*)(bias + col);
            *(float2*)(C + (size_t)row * DD + col) =
                make_float2(c[mt][nt][0] + bb.x, c[mt][nt][1] + bb.y);
            *(float2*)(C + (size_t)(row + 8) * DD + col) =
                make_float2(c[mt][nt][2] + bb.x, c[mt][nt][3] + bb.y);
        }
    }
}

// Fused Q/K/V projection: grid (24, 32); x-blocks 0-7 -> Q, 8-15 -> K, 16-23 -> V
__global__ __launch_bounds__(256, 2) void gemm_qkv(
    const float* __restrict__ x,
    const float* __restrict__ Wq, const float* __restrict__ Wk, const float* __restrict__ Wv,
    const float* __restrict__ bq, const float* __restrict__ bk, const float* __restrict__ bv,
    float* __restrict__ Q, float* __restrict__ K, float* __restrict__ V)
{
    __shared__ float As[2][128][20];
    __shared__ float Bs[2][16][136];

    int sel = blockIdx.x >> 3;
    const float* B    = (sel == 0) ? Wq : (sel == 1) ? Wk : Wv;
    const float* bias = (sel == 0) ? bq : (sel == 1) ? bk : bv;
    float*       C    = (sel == 0) ? Q  : (sel == 1) ? K  : V;
    int bn = (blockIdx.x & 7) * 128;
    int bm = blockIdx.y * 128;

    gemm_core<0>(As, Bs, x, B, bias, C, bm, bn, nullptr, nullptr, nullptr, nullptr);
}

// O projection with fused GroupNorm on the A operand
__global__ __launch_bounds__(256, 2) void gemm_o(
    const float* __restrict__ AO, const float* __restrict__ Wo,
    const float* __restrict__ bo, float* __restrict__ y,
    const float* __restrict__ mean, const float* __restrict__ rstd,
    const float* __restrict__ gnw, const float* __restrict__ gnb)
{
    __shared__ float As[2][128][20];
    __shared__ float Bs[2][16][136];
    gemm_core<1>(As, Bs, AO, Wo, bo, y,
                 blockIdx.y * 128, blockIdx.x * 128, mean, rstd, gnw, gnb);
}

// ---------------------------------------------------------------------------
// tf32 flash attention — round-12 proven config: Br=Bc=64, 128 threads,
// 4 warps, occ 4, 1024 CTAs (one tile each), cp.async phase-pipelined K/V,
// GN partial stats fused into epilogue.
// ---------------------------------------------------------------------------
#define FLASH_TILES (BB * HH * (SS / 64))   // 1024
#define NJ (SS / 64)                        // 32
#define FLASH_SMEM ((64*68 + 64*72 + 64*68) * 4)   // Ks, Vs, Ps = 53248 B

__global__ __launch_bounds__(128, 4) void flash_tf32(
    const float* __restrict__ Q, const float* __restrict__ K,
    const float* __restrict__ V, const float* __restrict__ lam,
    float* __restrict__ O, double* __restrict__ part)
{
    extern __shared__ float smf[];
    float (*Ks)[68] = (float(*)[68])(smf);
    float (*Vs)[72] = (float(*)[72])(smf + 64 * 68);
    float (*Ps)[68] = (float(*)[68])(smf + 64 * 68 + 64 * 72);

    const int tid  = threadIdx.x;
    const int warp = tid >> 5;
    const int lane = tid & 31;
    const int g    = lane >> 2;
    const int tig  = lane & 3;
    const int r_q  = (warp << 4) + g;

    const uint32_t ks_base = smem_u32(&Ks[0][0]);
    const uint32_t vs_base = smem_u32(&Vs[0][0]);

    int fr[8], fd[8];
    #pragma unroll
    for (int i = 0; i < 8; i++) {
        int idx = tid + i * 128;
        fr[i] = idx >> 4;
        fd[i] = (idx & 15) << 2;
    }

    const int tile = blockIdx.x;
    const int bh = tile >> 5;
    const int it = tile & 31;
    const int b  = bh >> 4;
    const int h  = bh & 15;
    const int i0 = it << 6;
    const float fac = 0.125f * lam[h] * 1.4426950408889634f;

    const float* kp0 = K + (size_t)b * SS * DD + h * DHH;
    const float* vp0 = V + (size_t)b * SS * DD + h * DHH;

    #pragma unroll
    for (int i = 0; i < 8; i++)
        cp_async16(ks_base + (uint32_t)(fr[i] * 68 + fd[i]) * 4,
                   kp0 + (size_t)fr[i] * DD + fd[i]);
    CP_COMMIT();
    #pragma unroll
    for (int i = 0; i < 8; i++)
        cp_async16(vs_base + (uint32_t)(fr[i] * 72 + fd[i]) * 4,
                   vp0 + (size_t)fr[i] * DD + fd[i]);
    CP_COMMIT();

    float q[8][4];
    {
        const float* qp = Q + (size_t)(b * SS + i0 + r_q) * DD + h * DHH;
        #pragma unroll
        for (int kt = 0; kt < 8; kt++) {
            q[kt][0] = to_tf32(qp[kt * 8 + tig] * fac);
            q[kt][1] = to_tf32(qp[8 * DD + kt * 8 + tig] * fac);
            q[kt][2] = to_tf32(qp[kt * 8 + tig + 4] * fac);
            q[kt][3] = to_tf32(qp[8 * DD + kt * 8 + tig + 4] * fac);
        }
    }

    float o[8][4];
    #pragma unroll
    for (int nt = 0; nt < 8; nt++)
        #pragma unroll
        for (int r = 0; r < 4; r++) o[nt][r] = 0.f;
    float m0 = -INFINITY, m1 = -INFINITY, l0 = 0.f, l1 = 0.f;

    for (int jt = 0; jt < NJ; jt++) {
        if (jt == NJ - 1) { CP_WAIT(0); } else { CP_WAIT(1); }
        __syncthreads();

        float s[8][4];
        #pragma unroll
        for (int nt = 0; nt < 8; nt++)
            #pragma unroll
            for (int r = 0; r < 4; r++) s[nt][r] = 0.f;

        #pragma unroll
        for (int kk = 0; kk < 8; kk++) {
            #pragma unroll
            for (int nt = 0; nt < 8; nt++) {
                float bfr[2];
                bfr[0] = Ks[nt * 8 + g][kk * 8 + tig];
                bfr[1] = Ks[nt * 8 + g][kk * 8 + tig + 4];
                mma_tf32(s[nt], q[kk], bfr);
            }
        }
        __syncthreads();

        if (jt + 1 < NJ) {
            const float* kp = kp0 + (size_t)(jt + 1) * 64 * DD;
            #pragma unroll
            for (int i = 0; i < 8; i++)
                cp_async16(ks_base + (uint32_t)(fr[i] * 68 + fd[i]) * 4,
                           kp + (size_t)fr[i] * DD + fd[i]);
            CP_COMMIT();
        }

        float mx0 = -INFINITY, mx1 = -INFINITY;
        #pragma unroll
        for (int nt = 0; nt < 8; nt++) {
            mx0 = fmaxf(mx0, fmaxf(s[nt][0], s[nt][1]));
            mx1 = fmaxf(mx1, fmaxf(s[nt][2], s[nt][3]));
        }
        mx0 = fmaxf(mx0, __shfl_xor_sync(0xffffffffu, mx0, 1));
        mx0 = fmaxf(mx0, __shfl_xor_sync(0xffffffffu, mx0, 2));
        mx1 = fmaxf(mx1, __shfl_xor_sync(0xffffffffu, mx1, 1));
        mx1 = fmaxf(mx1, __shfl_xor_sync(0xffffffffu, mx1, 2));

        float mn0 = fmaxf(m0, mx0);
        float mn1 = fmaxf(m1, mx1);
        float al0 = ex2(m0 - mn0);
        float al1 = ex2(m1 - mn1);
        float lt0 = 0.f, lt1 = 0.f;
        #pragma unroll
        for (int nt = 0; nt < 8; nt++) {
            s[nt][0] = ex2(s[nt][0] - mn0); lt0 += s[nt][0];
            s[nt][1] = ex2(s[nt][1] - mn0); lt0 += s[nt][1];
            s[nt][2] = ex2(s[nt][2] - mn1); lt1 += s[nt][2];
            s[nt][3] = ex2(s[nt][3] - mn1); lt1 += s[nt][3];
        }
        lt0 += __shfl_xor_sync(0xffffffffu, lt0, 1);
        lt0 += __shfl_xor_sync(0xffffffffu, lt0, 2);
        lt1 += __shfl_xor_sync(0xffffffffu, lt1, 1);
        lt1 += __shfl_xor_sync(0xffffffffu, lt1, 2);
        l0 = l0 * al0 + lt0;
        l1 = l1 * al1 + lt1;
        m0 = mn0;
        m1 = mn1;
        #pragma unroll
        for (int nt = 0; nt < 8; nt++) {
            o[nt][0] *= al0; o[nt][1] *= al0;
            o[nt][2] *= al1; o[nt][3] *= al1;
        }

        #pragma unroll
        for (int nt = 0; nt < 8; nt++) {
            Ps[r_q][nt * 8 + 2 * tig]         = to_tf32(s[nt][0]);
            Ps[r_q][nt * 8 + 2 * tig + 1]     = to_tf32(s[nt][1]);
            Ps[r_q + 8][nt * 8 + 2 * tig]     = to_tf32(s[nt][2]);
            Ps[r_q + 8][nt * 8 + 2 * tig + 1] = to_tf32(s[nt][3]);
        }
        __syncwarp();

        if (jt == NJ - 1) { CP_WAIT(0); } else { CP_WAIT(1); }
        __syncthreads();

        #pragma unroll
        for (int kk = 0; kk < 64; kk += 8) {
            float a[4];
            a[0] = Ps[r_q][kk + tig];
            a[1] = Ps[r_q + 8][kk + tig];
            a[2] = Ps[r_q][kk + tig + 4];
            a[3] = Ps[r_q + 8][kk + tig + 4];
            #pragma unroll
            for (int nt = 0; nt < 8; nt++) {
                float bfr[2];
                bfr[0] = Vs[kk + tig][nt * 8 + g];
                bfr[1] = Vs[kk + tig + 4][nt * 8 + g];
                mma_tf32(o[nt], a, bfr);
            }
        }
        __syncthreads();

        if (jt + 1 < NJ) {
            const float* vp = vp0 + (size_t)(jt + 1) * 64 * DD;
            #pragma unroll
            for (int i = 0; i < 8; i++)
                cp_async16(vs_base + (uint32_t)(fr[i] * 72 + fd[i]) * 4,
                           vp + (size_t)fr[i] * DD + fd[i]);
            CP_COMMIT();
        }
    }

    // epilogue: write O + fused GN partial stats
    float inv0 = 1.f / l0;
    float inv1 = 1.f / l1;
    float psum = 0.f, psq = 0.f;
    float* op0 = O + (size_t)(b * SS + i0 + r_q) * DD + h * DHH;
    float* op1 = op0 + 8 * DD;
    #pragma unroll
    for (int nt = 0; nt < 8; nt++) {
        float v0 = o[nt][0] * inv0, v1 = o[nt][1] * inv0;
        float v2 = o[nt][2] * inv1, v3 = o[nt][3] * inv1;
        *(float2*)(op0 + nt * 8 + 2 * tig) = make_float2(v0, v1);
        *(float2*)(op1 + nt * 8 + 2 * tig) = make_float2(v2, v3);
        psum += v0 + v1 + v2 + v3;
        psq  += v0 * v0 + v1 * v1 + v2 * v2 + v3 * v3;
    }
    double ds = (double)psum, dq = (double)psq;
    #pragma unroll
    for (int off = 16; off > 0; off >>= 1) {
        ds += __shfl_xor_sync(0xffffffffu, ds, off);
        dq += __shfl_xor_sync(0xffffffffu, dq, off);
    }
    __shared__ double wsum[4], wsq[4];
    if (lane == 0) { wsum[warp] = ds; wsq[warp] = dq; }
    __syncthreads();
    if (tid == 0) {
        double ts = wsum[0] + wsum[1] + wsum[2] + wsum[3];
        double tq = wsq[0] + wsq[1] + wsq[2] + wsq[3];
        part[tile * 2 + 0] = ts;
        part[tile * 2 + 1] = tq;
    }
}

// ---------------------------------------------------------------------------
// GN stats final: one block, 1024 threads; warp w reduces the 32 tile-partials
// of bh = w.
// ---------------------------------------------------------------------------
__global__ __launch_bounds__(1024) void gn_stats_final(const double* __restrict__ part,
                                                       float* __restrict__ mean,
                                                       float* __restrict__ rstd)
{
    int bh   = threadIdx.x >> 5;   // 0..31
    int lane = threadIdx.x & 31;
    double s = part[(bh * 32 + lane) * 2 + 0];
    double q = part[(bh * 32 + lane) * 2 + 1];
    #pragma unroll
    for (int off = 16; off > 0; off >>= 1) {
        s += __shfl_xor_sync(0xffffffffu, s, off);
        q += __shfl_xor_sync(0xffffffffu, q, off);
    }
    if (lane == 0) {
        double n = (double)SS * DHH;
        double mu = s / n;
        double var = q / n - mu * mu;
        mean[bh] = (float)mu;
        rstd[bh] = (float)(1.0 / sqrt(var + (double)GN_EPS));
    }
}

// ---------------------------------------------------------------------------
extern "C" void kernel_launch(void* const* d_in, const int* in_sizes, int n_in,
                              void* d_out, int out_size) {
    const float* x   = (const float*)d_in[0];
    const float* Wq  = (const float*)d_in[1];
    const float* bq  = (const float*)d_in[2];
    const float* Wk  = (const float*)d_in[3];
    const float* bk  = (const float*)d_in[4];
    const float* Wv  = (const float*)d_in[5];
    const float* bv  = (const float*)d_in[6];
    const float* Wo  = (const float*)d_in[7];
    const float* bo  = (const float*)d_in[8];
    const float* lq1 = (const float*)d_in[9];
    const float* lk1 = (const float*)d_in[10];
    const float* lq2 = (const float*)d_in[11];
    const float* lk2 = (const float*)d_in[12];
    const float* gnw = (const float*)d_in[13];
    const float* gnb = (const float*)d_in[14];
    float* y = (float*)d_out;

    float *Qp, *Kp, *Vp, *AOp, *Xrp, *Wrp, *lamp, *meanp, *rstdp;
    double* partp;
    cudaGetSymbolAddress((void**)&Qp,    g_Q);
    cudaGetSymbolAddress((void**)&Kp,    g_K);
    cudaGetSymbolAddress((void**)&Vp,    g_V);
    cudaGetSymbolAddress((void**)&AOp,   g_AO);
    cudaGetSymbolAddress((void**)&Xrp,   g_Xr);
    cudaGetSymbolAddress((void**)&Wrp,   g_Wr);
    cudaGetSymbolAddress((void**)&lamp,  g_lam);
    cudaGetSymbolAddress((void**)&meanp, g_mean);
    cudaGetSymbolAddress((void**)&rstdp, g_rstd);
    cudaGetSymbolAddress((void**)&partp, g_part);

    float* Wrq = Wrp;
    float* Wrk = Wrp + (size_t)DD * DD;
    float* Wrv = Wrp + (size_t)2 * DD * DD;
    float* Wro = Wrp + (size_t)3 * DD * DD;

    static int attr_set = 0;
    if (!attr_set) {
        cudaFuncSetAttribute(flash_tf32, cudaFuncAttributeMaxDynamicSharedMemorySize,
                             FLASH_SMEM);
        attr_set = 1;
    }

    // pre-round x + all 4 weights to rne tf32 in one launch
    // total float4s: MM*DD/4 + 4*DD*DD/4 = 1M + 1M = 2M -> 8192 blocks
    tf32_round_all<<<(MM * DD / 4 + DD * DD) / 256, 256>>>(x, Xrp, Wq, Wk, Wv, Wo, Wrp);

    lambda_kernel<<<1, HH * 32>>>(lq1, lk1, lq2, lk2, lamp);

    gemm_qkv<<<dim3(24, 32), 256>>>(Xrp, Wrq, Wrk, Wrv, bq, bk, bv, Qp, Kp, Vp);

    flash_tf32<<<FLASH_TILES, 128, FLASH_SMEM>>>(Qp, Kp, Vp, lamp, AOp, partp);

    gn_stats_final<<<1, 1024>>>(partp, meanp, rstdp);

    gemm_o<<<dim3(8, 32), 256>>>(AOp, Wro, bo, y, meanp, rstdp, gnw, gnb);
}

// round 16
// speedup vs baseline: 1.0634x; 1.0131x over previous
#include <cuda_runtime.h>
#include <math.h>
#include <stdint.h>

// Problem constants
#define BB 2
#define SS 2048
#define DD 1024
#define HH 16
#define DHH 64
#define MM (BB*SS)          // 4096 rows
#define LAMBDA_INIT 0.8f
#define GN_EPS 1e-5f

// Scratch (device globals; no allocation allowed)
__device__ float g_Q[MM*DD];
__device__ float g_K[MM*DD];
__device__ float g_V[MM*DD];
__device__ float g_AO[MM*DD];   // attention output [B,S,H,DH]
__device__ float g_Xr[MM*DD];   // rne-tf32 rounded x
__device__ float g_Wr[4][DD*DD];// rne-tf32 rounded Wq,Wk,Wv,Wo
__device__ float g_lam[HH];
__device__ float g_mean[BB*HH];
__device__ float g_rstd[BB*HH];
__device__ double g_part[BB*HH*32*2];   // per flash tile {sum,sumsq} (1024 tiles)

// ---------------------------------------------------------------------------
// helpers
// ---------------------------------------------------------------------------
__device__ __forceinline__ float to_tf32(float x) {
    unsigned u;
    asm("cvt.rna.tf32.f32 %0, %1;" : "=r"(u) : "f"(x));
    return __uint_as_float(u);
}
__device__ __forceinline__ float ex2(float x) {
    float r;
    asm("ex2.approx.ftz.f32 %0, %1;" : "=f"(r) : "f"(x));
    return r;
}
__device__ __forceinline__ uint32_t smem_u32(const void* p) {
    uint32_t a;
    asm("{ .reg .u64 t; cvta.to.shared.u64 t, %1; cvt.u32.u64 %0, t; }" : "=r"(a) : "l"(p));
    return a;
}
__device__ __forceinline__ void cp_async16(uint32_t dst, const void* src) {
    asm volatile("cp.async.cg.shared.global [%0], [%1], 16;" :: "r"(dst), "l"(src));
}
#define CP_COMMIT() asm volatile("cp.async.commit_group;" ::: "memory")
#define CP_WAIT(n)  asm volatile("cp.async.wait_group %0;" :: "n"(n) : "memory")

__device__ __forceinline__ void mma_tf32(float* c, const float* a, const float* b) {
    const unsigned* A = reinterpret_cast<const unsigned*>(a);
    const unsigned* B = reinterpret_cast<const unsigned*>(b);
    asm volatile(
        "mma.sync.aligned.m16n8k8.row.col.f32.tf32.tf32.f32 "
        "{%0,%1,%2,%3}, {%4,%5,%6,%7}, {%8,%9}, {%0,%1,%2,%3};\n"
        : "+f"(c[0]), "+f"(c[1]), "+f"(c[2]), "+f"(c[3])
        : "r"(A[0]), "r"(A[1]), "r"(A[2]), "r"(A[3]),
          "r"(B[0]), "r"(B[1]));
}

// ---------------------------------------------------------------------------
// merged rne-tf32 rounding: one launch covers x (1M float4) + 4 weights
// ---------------------------------------------------------------------------
__global__ __launch_bounds__(256) void tf32_round_all(
    const float* __restrict__ x, float* __restrict__ xr,
    const float* __restrict__ w0, const float* __restrict__ w1,
    const float* __restrict__ w2, const float* __restrict__ w3,
    float* __restrict__ wr)
{
    int i = blockIdx.x * 256 + threadIdx.x;   // 0 .. 2M-1 float4s
    const float* in;
    float* out;
    if (i < (MM * DD / 4)) {
        in = x + (size_t)i * 4;
        out = xr + (size_t)i * 4;
    } else {
        int j = i - (MM * DD / 4);
        int w = j >> 18;
        int k = j & 0x3FFFF;
        const float* ws = (w == 0) ? w0 : (w == 1) ? w1 : (w == 2) ? w2 : w3;
        in = ws + (size_t)k * 4;
        out = wr + (size_t)w * DD * DD + (size_t)k * 4;
    }
    float4 v = *(const float4*)in;
    v.x = to_tf32(v.x);
    v.y = to_tf32(v.y);
    v.z = to_tf32(v.z);
    v.w = to_tf32(v.w);
    *(float4*)out = v;
}

// ---------------------------------------------------------------------------
// lambda[h] = exp(<lq1,lk1>) - exp(<lq2,lk2>) + 0.8  (one warp/head)
// ---------------------------------------------------------------------------
__global__ void lambda_kernel(const float* __restrict__ lq1, const float* __restrict__ lk1,
                              const float* __restrict__ lq2, const float* __restrict__ lk2,
                              float* __restrict__ lam) {
    int h = threadIdx.x >> 5;
    int lane = threadIdx.x & 31;
    const float* a1 = lq1 + h * DHH;
    const float* b1 = lk1 + h * DHH;
    const float* a2 = lq2 + h * DHH;
    const float* b2 = lk2 + h * DHH;
    float s1 = a1[lane] * b1[lane] + a1[lane + 32] * b1[lane + 32];
    float s2 = a2[lane] * b2[lane] + a2[lane + 32] * b2[lane + 32];
    #pragma unroll
    for (int off = 16; off > 0; off >>= 1) {
        s1 += __shfl_xor_sync(0xffffffffu, s1, off);
        s2 += __shfl_xor_sync(0xffffffffu, s2, off);
    }
    if (lane == 0) lam[h] = expf(s1) - expf(s2) + LAMBDA_INIT;
}

// ---------------------------------------------------------------------------
// tf32 tensor-core GEMM core with cp.async operand staging (round-12 proven).
// BM=128 BN=128 BK=16, 256 threads = 8 warps (2x4), warp tile 64x32.
// FUSE=0: A and B both via cp.async (inputs PRE-ROUNDED rne tf32).
// FUSE=1: A via registers with GroupNorm transform + rne tf32; B via cp.async.
// ---------------------------------------------------------------------------
template<int FUSE>
__device__ __forceinline__ void gemm_core(
    float (*As)[128][20], float (*Bs)[16][136],
    const float* __restrict__ A, const float* __restrict__ B,
    const float* __restrict__ bias, float* __restrict__ C,
    int bm, int bn,
    const float* __restrict__ mean, const float* __restrict__ rstd,
    const float* __restrict__ gnw, const float* __restrict__ gnb)
{
    const int tid  = threadIdx.x;
    const int warp = tid >> 5;
    const int lane = tid & 31;
    const int g    = lane >> 2;
    const int tig  = lane & 3;
    const int wm   = warp >> 2;    // 0..1
    const int wn   = warp & 3;     // 0..3

    int arow[2], akc[2], bkr[2], bnc[2];
    #pragma unroll
    for (int i = 0; i < 2; i++) {
        int idx = tid + i * 256;
        arow[i] = idx >> 2;          // 0..127
        akc[i]  = (idx & 3) << 2;    // 0,4,8,12
        bkr[i]  = idx >> 5;          // 0..15
        bnc[i]  = (idx & 31) << 2;   // 0..124
    }

    float c[4][4][4];
    #pragma unroll
    for (int mt = 0; mt < 4; mt++)
        #pragma unroll
        for (int nt = 0; nt < 4; nt++)
            #pragma unroll
            for (int r = 0; r < 4; r++) c[mt][nt][r] = 0.f;

    const int NT = DD / 16;
    float4 fa[2];   // FUSE=1 A staging only

    auto issue_b = [&](int kt, int buf) {
        #pragma unroll
        for (int i = 0; i < 2; i++)
            cp_async16(smem_u32(&Bs[buf][bkr[i]][bnc[i]]),
                       B + (size_t)(kt + bkr[i]) * DD + bn + bnc[i]);
    };
    auto issue_a = [&](int kt, int buf) {
        #pragma unroll
        for (int i = 0; i < 2; i++)
            cp_async16(smem_u32(&As[buf][arow[i]][akc[i]]),
                       A + (size_t)(bm + arow[i]) * DD + kt + akc[i]);
    };
    auto fetch_a = [&](int kt) {
        #pragma unroll
        for (int i = 0; i < 2; i++) {
            fa[i] = *(const float4*)(A + (size_t)(bm + arow[i]) * DD + kt + akc[i]);
            int bi = (bm + arow[i]) >> 11;
            int k  = kt + akc[i];
            int hh = k >> 6;
            float mu = mean[bi * HH + hh];
            float rs = rstd[bi * HH + hh];
            float4 w  = *(const float4*)(gnw + k);
            float4 gb = *(const float4*)(gnb + k);
            fa[i].x = (fa[i].x - mu) * rs * w.x + gb.x;
            fa[i].y = (fa[i].y - mu) * rs * w.y + gb.y;
            fa[i].z = (fa[i].z - mu) * rs * w.z + gb.z;
            fa[i].w = (fa[i].w - mu) * rs * w.w + gb.w;
        }
    };
    auto store_a = [&](int buf) {
        #pragma unroll
        for (int i = 0; i < 2; i++) {
            As[buf][arow[i]][akc[i] + 0] = to_tf32(fa[i].x);
            As[buf][arow[i]][akc[i] + 1] = to_tf32(fa[i].y);
            As[buf][arow[i]][akc[i] + 2] = to_tf32(fa[i].z);
            As[buf][arow[i]][akc[i] + 3] = to_tf32(fa[i].w);
        }
    };

    // prologue: stage tile 0
    if (FUSE) {
        issue_b(0, 0);
        CP_COMMIT();
        fetch_a(0);
        store_a(0);
    } else {
        issue_a(0, 0);
        issue_b(0, 0);
        CP_COMMIT();
    }

    for (int t = 0; t < NT; t++) {
        int buf = t & 1;
        if (t + 1 < NT) {
            if (FUSE) {
                issue_b((t + 1) * 16, buf ^ 1);
                CP_COMMIT();
                fetch_a((t + 1) * 16);
            } else {
                issue_a((t + 1) * 16, buf ^ 1);
                issue_b((t + 1) * 16, buf ^ 1);
                CP_COMMIT();
            }
            CP_WAIT(1);
        } else {
            CP_WAIT(0);
        }
        __syncthreads();

        #pragma unroll
        for (int kk = 0; kk < 16; kk += 8) {
            float a[4][4], b[4][2];
            #pragma unroll
            for (int mt = 0; mt < 4; mt++) {
                int r0 = wm * 64 + mt * 16 + g;
                a[mt][0] = As[buf][r0][kk + tig];
                a[mt][1] = As[buf][r0 + 8][kk + tig];
                a[mt][2] = As[buf][r0][kk + tig + 4];
                a[mt][3] = As[buf][r0 + 8][kk + tig + 4];
            }
            #pragma unroll
            for (int nt = 0; nt < 4; nt++) {
                int cn = wn * 32 + nt * 8 + g;
                b[nt][0] = Bs[buf][kk + tig][cn];
                b[nt][1] = Bs[buf][kk + tig + 4][cn];
            }
            #pragma unroll
            for (int mt = 0; mt < 4; mt++)
                #pragma unroll
                for (int nt = 0; nt < 4; nt++)
                    mma_tf32(c[mt][nt], a[mt], b[nt]);
        }

        if (FUSE && t + 1 < NT) store_a(buf ^ 1);
        __syncthreads();
    }

    // epilogue + bias
    #pragma unroll
    for (int mt = 0; mt < 4; mt++) {
        int row = bm + wm * 64 + mt * 16 + g;
        #pragma unroll
        for (int nt = 0; nt < 4; nt++) {
            int col = bn + wn * 32 + nt * 8 + 2 * tig;
            float2 bb = *(const float2*)(bias + col);
            *(float2*)(C + (size_t)row * DD + col) =
                make_float2(c[mt][nt][0] + bb.x, c[mt][nt][1] + bb.y);
            *(float2*)(C + (size_t)(row + 8) * DD + col) =
                make_float2(c[mt][nt][2] + bb.x, c[mt][nt][3] + bb.y);
        }
    }
}

// Fused Q/K/V projection: grid (24, 32); x-blocks 0-7 -> Q, 8-15 -> K, 16-23 -> V
__global__ __launch_bounds__(256, 2) void gemm_qkv(
    const float* __restrict__ x,
    const float* __restrict__ Wq, const float* __restrict__ Wk, const float* __restrict__ Wv,
    const float* __restrict__ bq, const float* __restrict__ bk, const float* __restrict__ bv,
    float* __restrict__ Q, float* __restrict__ K, float* __restrict__ V)
{
    __shared__ float As[2][128][20];
    __shared__ float Bs[2][16][136];

    int sel = blockIdx.x >> 3;
    const float* B    = (sel == 0) ? Wq : (sel == 1) ? Wk : Wv;
    const float* bias = (sel == 0) ? bq : (sel == 1) ? bk : bv;
    float*       C    = (sel == 0) ? Q  : (sel == 1) ? K  : V;
    int bn = (blockIdx.x & 7) * 128;
    int bm = blockIdx.y * 128;

    gemm_core<0>(As, Bs, x, B, bias, C, bm, bn, nullptr, nullptr, nullptr, nullptr);
}

// O projection with fused GroupNorm on the A operand
__global__ __launch_bounds__(256, 2) void gemm_o(
    const float* __restrict__ AO, const float* __restrict__ Wo,
    const float* __restrict__ bo, float* __restrict__ y,
    const float* __restrict__ mean, const float* __restrict__ rstd,
    const float* __restrict__ gnw, const float* __restrict__ gnb)
{
    __shared__ float As[2][128][20];
    __shared__ float Bs[2][16][136];
    gemm_core<1>(As, Bs, AO, Wo, bo, y,
                 blockIdx.y * 128, blockIdx.x * 128, mean, rstd, gnw, gnb);
}

// ---------------------------------------------------------------------------
// tf32 flash attention — Br=Bc=64, 128 threads, 4 warps, occ 4, 1024 CTAs,
// cp.async phase-pipelined K/V, GN stats fused into epilogue.
// k-permutation (pos tig -> d=2*tig, pos tig+4 -> d=2*tig+1) gives:
//   - Ks B-fragments as single LDS.64 (stride 72: banks 8g+2t, conflict-free)
//   - PV A-fragment == S C-fragment (P never touches smem)
//   - Vs B-frag rows 2tig / 2tig+1 (stride 68: banks 8t+g / +4, conflict-free)
// ---------------------------------------------------------------------------
#define FLASH_TILES (BB * HH * (SS / 64))   // 1024
#define NJ (SS / 64)                        // 32
#define FLASH_SMEM ((64*72 + 64*68) * 4)    // Ks + Vs = 35840 B

__global__ __launch_bounds__(128, 4) void flash_tf32(
    const float* __restrict__ Q, const float* __restrict__ K,
    const float* __restrict__ V, const float* __restrict__ lam,
    float* __restrict__ O, double* __restrict__ part)
{
    extern __shared__ float smf[];
    float (*Ks)[72] = (float(*)[72])(smf);                 // [j][d], stride 72
    float (*Vs)[68] = (float(*)[68])(smf + 64 * 72);       // [j][d], stride 68

    const int tid  = threadIdx.x;
    const int warp = tid >> 5;
    const int lane = tid & 31;
    const int g    = lane >> 2;
    const int tig  = lane & 3;
    const int r_q  = (warp << 4) + g;

    const uint32_t ks_base = smem_u32(&Ks[0][0]);
    const uint32_t vs_base = smem_u32(&Vs[0][0]);

    int fr[8], fd[8];
    #pragma unroll
    for (int i = 0; i < 8; i++) {
        int idx = tid + i * 128;
        fr[i] = idx >> 4;
        fd[i] = (idx & 15) << 2;
    }

    const int tile = blockIdx.x;
    const int bh = tile >> 5;
    const int it = tile & 31;
    const int b  = bh >> 4;
    const int h  = bh & 15;
    const int i0 = it << 6;
    const float fac = 0.125f * lam[h] * 1.4426950408889634f;

    const float* kp0 = K + (size_t)b * SS * DD + h * DHH;
    const float* vp0 = V + (size_t)b * SS * DD + h * DHH;

    #pragma unroll
    for (int i = 0; i < 8; i++)
        cp_async16(ks_base + (uint32_t)(fr[i] * 72 + fd[i]) * 4,
                   kp0 + (size_t)fr[i] * DD + fd[i]);
    CP_COMMIT();
    #pragma unroll
    for (int i = 0; i < 8; i++)
        cp_async16(vs_base + (uint32_t)(fr[i] * 68 + fd[i]) * 4,
                   vp0 + (size_t)fr[i] * DD + fd[i]);
    CP_COMMIT();

    // Q fragments with permuted k gather: pos tig -> d=2tig, pos tig+4 -> d=2tig+1
    float q[8][4];
    {
        const float* qp = Q + (size_t)(b * SS + i0 + r_q) * DD + h * DHH;
        #pragma unroll
        for (int kt = 0; kt < 8; kt++) {
            q[kt][0] = to_tf32(qp[kt * 8 + 2 * tig] * fac);
            q[kt][1] = to_tf32(qp[8 * DD + kt * 8 + 2 * tig] * fac);
            q[kt][2] = to_tf32(qp[kt * 8 + 2 * tig + 1] * fac);
            q[kt][3] = to_tf32(qp[8 * DD + kt * 8 + 2 * tig + 1] * fac);
        }
    }

    float o[8][4];
    #pragma unroll
    for (int nt = 0; nt < 8; nt++)
        #pragma unroll
        for (int r = 0; r < 4; r++) o[nt][r] = 0.f;
    float m0 = -INFINITY, m1 = -INFINITY, l0 = 0.f, l1 = 0.f;

    for (int jt = 0; jt < NJ; jt++) {
        if (jt == NJ - 1) { CP_WAIT(0); } else { CP_WAIT(1); }
        __syncthreads();

        // ---- S = Q K^T (Ks fragments via LDS.64) ----
        float s[8][4];
        #pragma unroll
        for (int nt = 0; nt < 8; nt++)
            #pragma unroll
            for (int r = 0; r < 4; r++) s[nt][r] = 0.f;

        #pragma unroll
        for (int kk = 0; kk < 8; kk++) {
            #pragma unroll
            for (int nt = 0; nt < 8; nt++) {
                float2 kv = *(const float2*)&Ks[nt * 8 + g][kk * 8 + 2 * tig];
                float bfr[2] = {kv.x, kv.y};
                mma_tf32(s[nt], q[kk], bfr);
            }
        }
        __syncthreads();   // all warps done reading Ks

        if (jt + 1 < NJ) {
            const float* kp = kp0 + (size_t)(jt + 1) * 64 * DD;
            #pragma unroll
            for (int i = 0; i < 8; i++)
                cp_async16(ks_base + (uint32_t)(fr[i] * 72 + fd[i]) * 4,
                           kp + (size_t)fr[i] * DD + fd[i]);
            CP_COMMIT();
        }

        // ---- online softmax (log2 domain) ----
        float mx0 = -INFINITY, mx1 = -INFINITY;
        #pragma unroll
        for (int nt = 0; nt < 8; nt++) {
            mx0 = fmaxf(mx0, fmaxf(s[nt][0], s[nt][1]));
            mx1 = fmaxf(mx1, fmaxf(s[nt][2], s[nt][3]));
        }
        mx0 = fmaxf(mx0, __shfl_xor_sync(0xffffffffu, mx0, 1));
        mx0 = fmaxf(mx0, __shfl_xor_sync(0xffffffffu, mx0, 2));
        mx1 = fmaxf(mx1, __shfl_xor_sync(0xffffffffu, mx1, 1));
        mx1 = fmaxf(mx1, __shfl_xor_sync(0xffffffffu, mx1, 2));

        float mn0 = fmaxf(m0, mx0);
        float mn1 = fmaxf(m1, mx1);
        float al0 = ex2(m0 - mn0);
        float al1 = ex2(m1 - mn1);
        float lt0 = 0.f, lt1 = 0.f;
        #pragma unroll
        for (int nt = 0; nt < 8; nt++) {
            s[nt][0] = ex2(s[nt][0] - mn0); lt0 += s[nt][0];
            s[nt][1] = ex2(s[nt][1] - mn0); lt0 += s[nt][1];
            s[nt][2] = ex2(s[nt][2] - mn1); lt1 += s[nt][2];
            s[nt][3] = ex2(s[nt][3] - mn1); lt1 += s[nt][3];
        }
        lt0 += __shfl_xor_sync(0xffffffffu, lt0, 1);
        lt0 += __shfl_xor_sync(0xffffffffu, lt0, 2);
        lt1 += __shfl_xor_sync(0xffffffffu, lt1, 1);
        lt1 += __shfl_xor_sync(0xffffffffu, lt1, 2);
        l0 = l0 * al0 + lt0;
        l1 = l1 * al1 + lt1;
        m0 = mn0;
        m1 = mn1;
        #pragma unroll
        for (int nt = 0; nt < 8; nt++) {
            o[nt][0] *= al0; o[nt][1] *= al0;
            o[nt][2] *= al1; o[nt][3] *= al1;
        }

        // ---- V(jt) ready? ----
        if (jt == NJ - 1) { CP_WAIT(0); } else { CP_WAIT(1); }
        __syncthreads();

        // ---- O += P @ V : P A-fragment IS the S c-fragment (permuted k) ----
        #pragma unroll
        for (int kk8 = 0; kk8 < 8; kk8++) {
            float a[4];
            a[0] = to_tf32(s[kk8][0]);   // row g,   j = kk8*8 + 2tig
            a[1] = to_tf32(s[kk8][2]);   // row g+8, j = kk8*8 + 2tig
            a[2] = to_tf32(s[kk8][1]);   // row g,   j = kk8*8 + 2tig+1
            a[3] = to_tf32(s[kk8][3]);   // row g+8, j = kk8*8 + 2tig+1
            #pragma unroll
            for (int nt = 0; nt < 8; nt++) {
                float bfr[2];
                bfr[0] = Vs[kk8 * 8 + 2 * tig][nt * 8 + g];
                bfr[1] = Vs[kk8 * 8 + 2 * tig + 1][nt * 8 + g];
                mma_tf32(o[nt], a, bfr);
            }
        }
        __syncthreads();   // all warps done reading Vs

        if (jt + 1 < NJ) {
            const float* vp = vp0 + (size_t)(jt + 1) * 64 * DD;
            #pragma unroll
            for (int i = 0; i < 8; i++)
                cp_async16(vs_base + (uint32_t)(fr[i] * 68 + fd[i]) * 4,
                           vp + (size_t)fr[i] * DD + fd[i]);
            CP_COMMIT();
        }
    }

    // epilogue: write O + fused GN partial stats
    float inv0 = 1.f / l0;
    float inv1 = 1.f / l1;
    float psum = 0.f, psq = 0.f;
    float* op0 = O + (size_t)(b * SS + i0 + r_q) * DD + h * DHH;
    float* op1 = op0 + 8 * DD;
    #pragma unroll
    for (int nt = 0; nt < 8; nt++) {
        float v0 = o[nt][0] * inv0, v1 = o[nt][1] * inv0;
        float v2 = o[nt][2] * inv1, v3 = o[nt][3] * inv1;
        *(float2*)(op0 + nt * 8 + 2 * tig) = make_float2(v0, v1);
        *(float2*)(op1 + nt * 8 + 2 * tig) = make_float2(v2, v3);
        psum += v0 + v1 + v2 + v3;
        psq  += v0 * v0 + v1 * v1 + v2 * v2 + v3 * v3;
    }
    double ds = (double)psum, dq = (double)psq;
    #pragma unroll
    for (int off = 16; off > 0; off >>= 1) {
        ds += __shfl_xor_sync(0xffffffffu, ds, off);
        dq += __shfl_xor_sync(0xffffffffu, dq, off);
    }
    __shared__ double wsum[4], wsq[4];
    if (lane == 0) { wsum[warp] = ds; wsq[warp] = dq; }
    __syncthreads();
    if (tid == 0) {
        double ts = wsum[0] + wsum[1] + wsum[2] + wsum[3];
        double tq = wsq[0] + wsq[1] + wsq[2] + wsq[3];
        part[tile * 2 + 0] = ts;
        part[tile * 2 + 1] = tq;
    }
}

// ---------------------------------------------------------------------------
// GN stats final: one block, 1024 threads; warp w reduces the 32 tile-partials
// of bh = w.
// ---------------------------------------------------------------------------
__global__ __launch_bounds__(1024) void gn_stats_final(const double* __restrict__ part,
                                                       float* __restrict__ mean,
                                                       float* __restrict__ rstd)
{
    int bh   = threadIdx.x >> 5;   // 0..31
    int lane = threadIdx.x & 31;
    double s = part[(bh * 32 + lane) * 2 + 0];
    double q = part[(bh * 32 + lane) * 2 + 1];
    #pragma unroll
    for (int off = 16; off > 0; off >>= 1) {
        s += __shfl_xor_sync(0xffffffffu, s, off);
        q += __shfl_xor_sync(0xffffffffu, q, off);
    }
    if (lane == 0) {
        double n = (double)SS * DHH;
        double mu = s / n;
        double var = q / n - mu * mu;
        mean[bh] = (float)mu;
        rstd[bh] = (float)(1.0 / sqrt(var + (double)GN_EPS));
    }
}

// ---------------------------------------------------------------------------
extern "C" void kernel_launch(void* const* d_in, const int* in_sizes, int n_in,
                              void* d_out, int out_size) {
    const float* x   = (const float*)d_in[0];
    const float* Wq  = (const float*)d_in[1];
    const float* bq  = (const float*)d_in[2];
    const float* Wk  = (const float*)d_in[3];
    const float* bk  = (const float*)d_in[4];
    const float* Wv  = (const float*)d_in[5];
    const float* bv  = (const float*)d_in[6];
    const float* Wo  = (const float*)d_in[7];
    const float* bo  = (const float*)d_in[8];
    const float* lq1 = (const float*)d_in[9];
    const float* lk1 = (const float*)d_in[10];
    const float* lq2 = (const float*)d_in[11];
    const float* lk2 = (const float*)d_in[12];
    const float* gnw = (const float*)d_in[13];
    const float* gnb = (const float*)d_in[14];
    float* y = (float*)d_out;

    float *Qp, *Kp, *Vp, *AOp, *Xrp, *Wrp, *lamp, *meanp, *rstdp;
    double* partp;
    cudaGetSymbolAddress((void**)&Qp,    g_Q);
    cudaGetSymbolAddress((void**)&Kp,    g_K);
    cudaGetSymbolAddress((void**)&Vp,    g_V);
    cudaGetSymbolAddress((void**)&AOp,   g_AO);
    cudaGetSymbolAddress((void**)&Xrp,   g_Xr);
    cudaGetSymbolAddress((void**)&Wrp,   g_Wr);
    cudaGetSymbolAddress((void**)&lamp,  g_lam);
    cudaGetSymbolAddress((void**)&meanp, g_mean);
    cudaGetSymbolAddress((void**)&rstdp, g_rstd);
    cudaGetSymbolAddress((void**)&partp, g_part);

    float* Wrq = Wrp;
    float* Wrk = Wrp + (size_t)DD * DD;
    float* Wrv = Wrp + (size_t)2 * DD * DD;
    float* Wro = Wrp + (size_t)3 * DD * DD;

    static int attr_set = 0;
    if (!attr_set) {
        cudaFuncSetAttribute(flash_tf32, cudaFuncAttributeMaxDynamicSharedMemorySize,
                             FLASH_SMEM);
        attr_set = 1;
    }

    // pre-round x + all 4 weights to rne tf32 in one launch
    tf32_round_all<<<(MM * DD / 4 + DD * DD) / 256, 256>>>(x, Xrp, Wq, Wk, Wv, Wo, Wrp);

    lambda_kernel<<<1, HH * 32>>>(lq1, lk1, lq2, lk2, lamp);

    gemm_qkv<<<dim3(24, 32), 256>>>(Xrp, Wrq, Wrk, Wrv, bq, bk, bv, Qp, Kp, Vp);

    flash_tf32<<<FLASH_TILES, 128, FLASH_SMEM>>>(Qp, Kp, Vp, lamp, AOp, partp);

    gn_stats_final<<<1, 1024>>>(partp, meanp, rstdp);

    gemm_o<<<dim3(8, 32), 256>>>(AOp, Wro, bo, y, meanp, rstdp, gnw, gnb);
}

// round 17
// speedup vs baseline: 1.0868x; 1.0220x over previous
#include <cuda_runtime.h>
#include <math.h>
#include <stdint.h>

// Problem constants
#define BB 2
#define SS 2048
#define DD 1024
#define HH 16
#define DHH 64
#define MM (BB*SS)          // 4096 rows
#define LAMBDA_INIT 0.8f
#define GN_EPS 1e-5f

// Scratch (device globals; no allocation allowed)
__device__ float g_Q[MM*DD];
__device__ float g_K[MM*DD];
__device__ float g_V[MM*DD];
__device__ float g_AO[MM*DD];   // attention output [B,S,H,DH]
__device__ float g_Xr[MM*DD];   // rne-tf32 rounded x
__device__ float g_Wr[4][DD*DD];// rne-tf32 rounded Wq,Wk,Wv,Wo
__device__ float g_lam[HH];
__device__ double g_part[BB*HH*32*2];   // per flash tile {sum,sumsq} (1024 tiles)

// ---------------------------------------------------------------------------
// helpers
// ---------------------------------------------------------------------------
__device__ __forceinline__ float to_tf32(float x) {
    unsigned u;
    asm("cvt.rna.tf32.f32 %0, %1;" : "=r"(u) : "f"(x));
    return __uint_as_float(u);
}
__device__ __forceinline__ float ex2(float x) {
    float r;
    asm("ex2.approx.ftz.f32 %0, %1;" : "=f"(r) : "f"(x));
    return r;
}
__device__ __forceinline__ uint32_t smem_u32(const void* p) {
    uint32_t a;
    asm("{ .reg .u64 t; cvta.to.shared.u64 t, %1; cvt.u32.u64 %0, t; }" : "=r"(a) : "l"(p));
    return a;
}
__device__ __forceinline__ void cp_async16(uint32_t dst, const void* src) {
    asm volatile("cp.async.cg.shared.global [%0], [%1], 16;" :: "r"(dst), "l"(src));
}
#define CP_COMMIT() asm volatile("cp.async.commit_group;" ::: "memory")
#define CP_WAIT(n)  asm volatile("cp.async.wait_group %0;" :: "n"(n) : "memory")

__device__ __forceinline__ void mma_tf32(float* c, const float* a, const float* b) {
    const unsigned* A = reinterpret_cast<const unsigned*>(a);
    const unsigned* B = reinterpret_cast<const unsigned*>(b);
    asm volatile(
        "mma.sync.aligned.m16n8k8.row.col.f32.tf32.tf32.f32 "
        "{%0,%1,%2,%3}, {%4,%5,%6,%7}, {%8,%9}, {%0,%1,%2,%3};\n"
        : "+f"(c[0]), "+f"(c[1]), "+f"(c[2]), "+f"(c[3])
        : "r"(A[0]), "r"(A[1]), "r"(A[2]), "r"(A[3]),
          "r"(B[0]), "r"(B[1]));
}

// ---------------------------------------------------------------------------
// merged rne-tf32 rounding + lambda: blocks [0, NR) round x + 4 weights;
// block NR computes lambda[h] (16 threads per head, shfl tree).
// ---------------------------------------------------------------------------
#define NR_BLOCKS ((MM * DD / 4 + DD * DD) / 256)   // 8192

__global__ __launch_bounds__(256) void tf32_round_all(
    const float* __restrict__ x, float* __restrict__ xr,
    const float* __restrict__ w0, const float* __restrict__ w1,
    const float* __restrict__ w2, const float* __restrict__ w3,
    float* __restrict__ wr,
    const float* __restrict__ lq1, const float* __restrict__ lk1,
    const float* __restrict__ lq2, const float* __restrict__ lk2,
    float* __restrict__ lam)
{
    if (blockIdx.x == NR_BLOCKS) {
        // lambda: 16 threads per head
        int tid = threadIdx.x;
        int h = tid >> 4;
        int e = tid & 15;
        const float* a1 = lq1 + h * DHH;
        const float* b1 = lk1 + h * DHH;
        const float* a2 = lq2 + h * DHH;
        const float* b2 = lk2 + h * DHH;
        float s1 = 0.f, s2 = 0.f;
        #pragma unroll
        for (int d = 0; d < 4; d++) {
            s1 += a1[e + d * 16] * b1[e + d * 16];
            s2 += a2[e + d * 16] * b2[e + d * 16];
        }
        #pragma unroll
        for (int off = 8; off > 0; off >>= 1) {
            s1 += __shfl_xor_sync(0xffffffffu, s1, off);
            s2 += __shfl_xor_sync(0xffffffffu, s2, off);
        }
        if (e == 0) lam[h] = expf(s1) - expf(s2) + LAMBDA_INIT;
        return;
    }

    int i = blockIdx.x * 256 + threadIdx.x;   // 0 .. 2M-1 float4s
    const float* in;
    float* out;
    if (i < (MM * DD / 4)) {
        in = x + (size_t)i * 4;
        out = xr + (size_t)i * 4;
    } else {
        int j = i - (MM * DD / 4);
        int w = j >> 18;
        int k = j & 0x3FFFF;
        const float* ws = (w == 0) ? w0 : (w == 1) ? w1 : (w == 2) ? w2 : w3;
        in = ws + (size_t)k * 4;
        out = wr + (size_t)w * DD * DD + (size_t)k * 4;
    }
    float4 v = *(const float4*)in;
    v.x = to_tf32(v.x);
    v.y = to_tf32(v.y);
    v.z = to_tf32(v.z);
    v.w = to_tf32(v.w);
    *(float4*)out = v;
}

// ---------------------------------------------------------------------------
// tf32 tensor-core GEMM core with cp.async operand staging (round-12 proven).
// BM=128 BN=128 BK=16, 256 threads = 8 warps (2x4), warp tile 64x32.
// FUSE=0: A and B both via cp.async (inputs PRE-ROUNDED rne tf32).
// FUSE=1: A via registers with GroupNorm transform + rne tf32; B via cp.async.
// ---------------------------------------------------------------------------
template<int FUSE>
__device__ __forceinline__ void gemm_core(
    float (*As)[128][20], float (*Bs)[16][136],
    const float* __restrict__ A, const float* __restrict__ B,
    const float* __restrict__ bias, float* __restrict__ C,
    int bm, int bn,
    const float* mean, const float* rstd,
    const float* __restrict__ gnw, const float* __restrict__ gnb)
{
    const int tid  = threadIdx.x;
    const int warp = tid >> 5;
    const int lane = tid & 31;
    const int g    = lane >> 2;
    const int tig  = lane & 3;
    const int wm   = warp >> 2;    // 0..1
    const int wn   = warp & 3;     // 0..3

    int arow[2], akc[2], bkr[2], bnc[2];
    #pragma unroll
    for (int i = 0; i < 2; i++) {
        int idx = tid + i * 256;
        arow[i] = idx >> 2;          // 0..127
        akc[i]  = (idx & 3) << 2;    // 0,4,8,12
        bkr[i]  = idx >> 5;          // 0..15
        bnc[i]  = (idx & 31) << 2;   // 0..124
    }

    float c[4][4][4];
    #pragma unroll
    for (int mt = 0; mt < 4; mt++)
        #pragma unroll
        for (int nt = 0; nt < 4; nt++)
            #pragma unroll
            for (int r = 0; r < 4; r++) c[mt][nt][r] = 0.f;

    const int NT = DD / 16;
    float4 fa[2];   // FUSE=1 A staging only

    auto issue_b = [&](int kt, int buf) {
        #pragma unroll
        for (int i = 0; i < 2; i++)
            cp_async16(smem_u32(&Bs[buf][bkr[i]][bnc[i]]),
                       B + (size_t)(kt + bkr[i]) * DD + bn + bnc[i]);
    };
    auto issue_a = [&](int kt, int buf) {
        #pragma unroll
        for (int i = 0; i < 2; i++)
            cp_async16(smem_u32(&As[buf][arow[i]][akc[i]]),
                       A + (size_t)(bm + arow[i]) * DD + kt + akc[i]);
    };
    auto fetch_a = [&](int kt) {
        #pragma unroll
        for (int i = 0; i < 2; i++) {
            fa[i] = *(const float4*)(A + (size_t)(bm + arow[i]) * DD + kt + akc[i]);
            int bi = (bm + arow[i]) >> 11;
            int k  = kt + akc[i];
            int hh = k >> 6;
            float mu = mean[bi * HH + hh];
            float rs = rstd[bi * HH + hh];
            float4 w  = *(const float4*)(gnw + k);
            float4 gb = *(const float4*)(gnb + k);
            fa[i].x = (fa[i].x - mu) * rs * w.x + gb.x;
            fa[i].y = (fa[i].y - mu) * rs * w.y + gb.y;
            fa[i].z = (fa[i].z - mu) * rs * w.z + gb.z;
            fa[i].w = (fa[i].w - mu) * rs * w.w + gb.w;
        }
    };
    auto store_a = [&](int buf) {
        #pragma unroll
        for (int i = 0; i < 2; i++) {
            As[buf][arow[i]][akc[i] + 0] = to_tf32(fa[i].x);
            As[buf][arow[i]][akc[i] + 1] = to_tf32(fa[i].y);
            As[buf][arow[i]][akc[i] + 2] = to_tf32(fa[i].z);
            As[buf][arow[i]][akc[i] + 3] = to_tf32(fa[i].w);
        }
    };

    // prologue: stage tile 0
    if (FUSE) {
        issue_b(0, 0);
        CP_COMMIT();
        fetch_a(0);
        store_a(0);
    } else {
        issue_a(0, 0);
        issue_b(0, 0);
        CP_COMMIT();
    }

    for (int t = 0; t < NT; t++) {
        int buf = t & 1;
        if (t + 1 < NT) {
            if (FUSE) {
                issue_b((t + 1) * 16, buf ^ 1);
                CP_COMMIT();
                fetch_a((t + 1) * 16);
            } else {
                issue_a((t + 1) * 16, buf ^ 1);
                issue_b((t + 1) * 16, buf ^ 1);
                CP_COMMIT();
            }
            CP_WAIT(1);
        } else {
            CP_WAIT(0);
        }
        __syncthreads();

        #pragma unroll
        for (int kk = 0; kk < 16; kk += 8) {
            float a[4][4], b[4][2];
            #pragma unroll
            for (int mt = 0; mt < 4; mt++) {
                int r0 = wm * 64 + mt * 16 + g;
                a[mt][0] = As[buf][r0][kk + tig];
                a[mt][1] = As[buf][r0 + 8][kk + tig];
                a[mt][2] = As[buf][r0][kk + tig + 4];
                a[mt][3] = As[buf][r0 + 8][kk + tig + 4];
            }
            #pragma unroll
            for (int nt = 0; nt < 4; nt++) {
                int cn = wn * 32 + nt * 8 + g;
                b[nt][0] = Bs[buf][kk + tig][cn];
                b[nt][1] = Bs[buf][kk + tig + 4][cn];
            }
            #pragma unroll
            for (int mt = 0; mt < 4; mt++)
                #pragma unroll
                for (int nt = 0; nt < 4; nt++)
                    mma_tf32(c[mt][nt], a[mt], b[nt]);
        }

        if (FUSE && t + 1 < NT) store_a(buf ^ 1);
        __syncthreads();
    }

    // epilogue + bias
    #pragma unroll
    for (int mt = 0; mt < 4; mt++) {
        int row = bm + wm * 64 + mt * 16 + g;
        #pragma unroll
        for (int nt = 0; nt < 4; nt++) {
            int col = bn + wn * 32 + nt * 8 + 2 * tig;
            float2 bb = *(const float2*)(bias + col);
            *(float2*)(C + (size_t)row * DD + col) =
                make_float2(c[mt][nt][0] + bb.x, c[mt][nt][1] + bb.y);
            *(float2*)(C + (size_t)(row + 8) * DD + col) =
                make_float2(c[mt][nt][2] + bb.x, c[mt][nt][3] + bb.y);
        }
    }
}

// Fused Q/K/V projection: grid (24, 32); x-blocks 0-7 -> Q, 8-15 -> K, 16-23 -> V
__global__ __launch_bounds__(256, 2) void gemm_qkv(
    const float* __restrict__ x,
    const float* __restrict__ Wq, const float* __restrict__ Wk, const float* __restrict__ Wv,
    const float* __restrict__ bq, const float* __restrict__ bk, const float* __restrict__ bv,
    float* __restrict__ Q, float* __restrict__ K, float* __restrict__ V)
{
    __shared__ float As[2][128][20];
    __shared__ float Bs[2][16][136];

    int sel = blockIdx.x >> 3;
    const float* B    = (sel == 0) ? Wq : (sel == 1) ? Wk : Wv;
    const float* bias = (sel == 0) ? bq : (sel == 1) ? bk : bv;
    float*       C    = (sel == 0) ? Q  : (sel == 1) ? K  : V;
    int bn = (blockIdx.x & 7) * 128;
    int bm = blockIdx.y * 128;

    gemm_core<0>(As, Bs, x, B, bias, C, bm, bn, nullptr, nullptr, nullptr, nullptr);
}

// O projection with fused GroupNorm on the A operand; GN stats reduced from
// per-tile partials in the prologue (removes the gn_stats_final launch).
__global__ __launch_bounds__(256, 2) void gemm_o(
    const float* __restrict__ AO, const float* __restrict__ Wo,
    const float* __restrict__ bo, float* __restrict__ y,
    const double* __restrict__ part,
    const float* __restrict__ gnw, const float* __restrict__ gnb)
{
    __shared__ float As[2][128][20];
    __shared__ float Bs[2][16][136];
    __shared__ float smean[BB*HH], srstd[BB*HH];

    // reduce 32 partials per bh: 256 threads = 32 bh x 8 lanes, 4 partials each
    {
        int tid = threadIdx.x;
        int bh = tid >> 3;       // 0..31
        int j  = tid & 7;        // 0..7
        double s = 0.0, q = 0.0;
        #pragma unroll
        for (int jj = 0; jj < 4; jj++) {
            int p = bh * 32 + j * 4 + jj;
            s += part[p * 2 + 0];
            q += part[p * 2 + 1];
        }
        #pragma unroll
        for (int off = 4; off > 0; off >>= 1) {
            s += __shfl_xor_sync(0xffffffffu, s, off);
            q += __shfl_xor_sync(0xffffffffu, q, off);
        }
        if (j == 0) {
            double n = (double)SS * DHH;
            double mu = s / n;
            double var = q / n - mu * mu;
            smean[bh] = (float)mu;
            srstd[bh] = (float)(1.0 / sqrt(var + (double)GN_EPS));
        }
    }
    __syncthreads();

    gemm_core<1>(As, Bs, AO, Wo, bo, y,
                 blockIdx.y * 128, blockIdx.x * 128, smean, srstd, gnw, gnb);
}

// ---------------------------------------------------------------------------
// tf32 flash attention — Br=Bc=64, 128 threads, 4 warps, occ 4, 1024 CTAs,
// cp.async phase-pipelined K/V, GN stats fused into epilogue.
// k-permutation (pos tig -> d=2*tig, pos tig+4 -> d=2*tig+1):
//   Ks B-fragments via LDS.64; PV A-fragment == S C-fragment (no P smem).
// ---------------------------------------------------------------------------
#define FLASH_TILES (BB * HH * (SS / 64))   // 1024
#define NJ (SS / 64)                        // 32
#define FLASH_SMEM ((64*72 + 64*68) * 4)    // Ks + Vs = 35840 B

__global__ __launch_bounds__(128, 4) void flash_tf32(
    const float* __restrict__ Q, const float* __restrict__ K,
    const float* __restrict__ V, const float* __restrict__ lam,
    float* __restrict__ O, double* __restrict__ part)
{
    extern __shared__ float smf[];
    float (*Ks)[72] = (float(*)[72])(smf);                 // [j][d], stride 72
    float (*Vs)[68] = (float(*)[68])(smf + 64 * 72);       // [j][d], stride 68

    const int tid  = threadIdx.x;
    const int warp = tid >> 5;
    const int lane = tid & 31;
    const int g    = lane >> 2;
    const int tig  = lane & 3;
    const int r_q  = (warp << 4) + g;

    const uint32_t ks_base = smem_u32(&Ks[0][0]);
    const uint32_t vs_base = smem_u32(&Vs[0][0]);

    int fr[8], fd[8];
    #pragma unroll
    for (int i = 0; i < 8; i++) {
        int idx = tid + i * 128;
        fr[i] = idx >> 4;
        fd[i] = (idx & 15) << 2;
    }

    const int tile = blockIdx.x;
    const int bh = tile >> 5;
    const int it = tile & 31;
    const int b  = bh >> 4;
    const int h  = bh & 15;
    const int i0 = it << 6;
    const float fac = 0.125f * lam[h] * 1.4426950408889634f;

    const float* kp0 = K + (size_t)b * SS * DD + h * DHH;
    const float* vp0 = V + (size_t)b * SS * DD + h * DHH;

    #pragma unroll
    for (int i = 0; i < 8; i++)
        cp_async16(ks_base + (uint32_t)(fr[i] * 72 + fd[i]) * 4,
                   kp0 + (size_t)fr[i] * DD + fd[i]);
    CP_COMMIT();
    #pragma unroll
    for (int i = 0; i < 8; i++)
        cp_async16(vs_base + (uint32_t)(fr[i] * 68 + fd[i]) * 4,
                   vp0 + (size_t)fr[i] * DD + fd[i]);
    CP_COMMIT();

    // Q fragments with permuted k gather
    float q[8][4];
    {
        const float* qp = Q + (size_t)(b * SS + i0 + r_q) * DD + h * DHH;
        #pragma unroll
        for (int kt = 0; kt < 8; kt++) {
            q[kt][0] = to_tf32(qp[kt * 8 + 2 * tig] * fac);
            q[kt][1] = to_tf32(qp[8 * DD + kt * 8 + 2 * tig] * fac);
            q[kt][2] = to_tf32(qp[kt * 8 + 2 * tig + 1] * fac);
            q[kt][3] = to_tf32(qp[8 * DD + kt * 8 + 2 * tig + 1] * fac);
        }
    }

    float o[8][4];
    #pragma unroll
    for (int nt = 0; nt < 8; nt++)
        #pragma unroll
        for (int r = 0; r < 4; r++) o[nt][r] = 0.f;
    float m0 = -INFINITY, m1 = -INFINITY, l0 = 0.f, l1 = 0.f;

    for (int jt = 0; jt < NJ; jt++) {
        if (jt == NJ - 1) { CP_WAIT(0); } else { CP_WAIT(1); }
        __syncthreads();

        // ---- S = Q K^T (Ks fragments via LDS.64) ----
        float s[8][4];
        #pragma unroll
        for (int nt = 0; nt < 8; nt++)
            #pragma unroll
            for (int r = 0; r < 4; r++) s[nt][r] = 0.f;

        #pragma unroll
        for (int kk = 0; kk < 8; kk++) {
            #pragma unroll
            for (int nt = 0; nt < 8; nt++) {
                float2 kv = *(const float2*)&Ks[nt * 8 + g][kk * 8 + 2 * tig];
                float bfr[2] = {kv.x, kv.y};
                mma_tf32(s[nt], q[kk], bfr);
            }
        }
        __syncthreads();   // all warps done reading Ks

        if (jt + 1 < NJ) {
            const float* kp = kp0 + (size_t)(jt + 1) * 64 * DD;
            #pragma unroll
            for (int i = 0; i < 8; i++)
                cp_async16(ks_base + (uint32_t)(fr[i] * 72 + fd[i]) * 4,
                           kp + (size_t)fr[i] * DD + fd[i]);
            CP_COMMIT();
        }

        // ---- online softmax (log2 domain) ----
        float mx0 = -INFINITY, mx1 = -INFINITY;
        #pragma unroll
        for (int nt = 0; nt < 8; nt++) {
            mx0 = fmaxf(mx0, fmaxf(s[nt][0], s[nt][1]));
            mx1 = fmaxf(mx1, fmaxf(s[nt][2], s[nt][3]));
        }
        mx0 = fmaxf(mx0, __shfl_xor_sync(0xffffffffu, mx0, 1));
        mx0 = fmaxf(mx0, __shfl_xor_sync(0xffffffffu, mx0, 2));
        mx1 = fmaxf(mx1, __shfl_xor_sync(0xffffffffu, mx1, 1));
        mx1 = fmaxf(mx1, __shfl_xor_sync(0xffffffffu, mx1, 2));

        float mn0 = fmaxf(m0, mx0);
        float mn1 = fmaxf(m1, mx1);
        float al0 = ex2(m0 - mn0);
        float al1 = ex2(m1 - mn1);
        float lt0 = 0.f, lt1 = 0.f;
        #pragma unroll
        for (int nt = 0; nt < 8; nt++) {
            s[nt][0] = ex2(s[nt][0] - mn0); lt0 += s[nt][0];
            s[nt][1] = ex2(s[nt][1] - mn0); lt0 += s[nt][1];
            s[nt][2] = ex2(s[nt][2] - mn1); lt1 += s[nt][2];
            s[nt][3] = ex2(s[nt][3] - mn1); lt1 += s[nt][3];
        }
        lt0 += __shfl_xor_sync(0xffffffffu, lt0, 1);
        lt0 += __shfl_xor_sync(0xffffffffu, lt0, 2);
        lt1 += __shfl_xor_sync(0xffffffffu, lt1, 1);
        lt1 += __shfl_xor_sync(0xffffffffu, lt1, 2);
        l0 = l0 * al0 + lt0;
        l1 = l1 * al1 + lt1;
        m0 = mn0;
        m1 = mn1;
        #pragma unroll
        for (int nt = 0; nt < 8; nt++) {
            o[nt][0] *= al0; o[nt][1] *= al0;
            o[nt][2] *= al1; o[nt][3] *= al1;
        }

        // ---- V(jt) ready? ----
        if (jt == NJ - 1) { CP_WAIT(0); } else { CP_WAIT(1); }
        __syncthreads();

        // ---- O += P @ V : P A-fragment IS the S c-fragment (permuted k) ----
        #pragma unroll
        for (int kk8 = 0; kk8 < 8; kk8++) {
            float a[4];
            a[0] = to_tf32(s[kk8][0]);
            a[1] = to_tf32(s[kk8][2]);
            a[2] = to_tf32(s[kk8][1]);
            a[3] = to_tf32(s[kk8][3]);
            #pragma unroll
            for (int nt = 0; nt < 8; nt++) {
                float bfr[2];
                bfr[0] = Vs[kk8 * 8 + 2 * tig][nt * 8 + g];
                bfr[1] = Vs[kk8 * 8 + 2 * tig + 1][nt * 8 + g];
                mma_tf32(o[nt], a, bfr);
            }
        }
        __syncthreads();   // all warps done reading Vs

        if (jt + 1 < NJ) {
            const float* vp = vp0 + (size_t)(jt + 1) * 64 * DD;
            #pragma unroll
            for (int i = 0; i < 8; i++)
                cp_async16(vs_base + (uint32_t)(fr[i] * 68 + fd[i]) * 4,
                           vp + (size_t)fr[i] * DD + fd[i]);
            CP_COMMIT();
        }
    }

    // epilogue: write O + fused GN partial stats
    float inv0 = 1.f / l0;
    float inv1 = 1.f / l1;
    float psum = 0.f, psq = 0.f;
    float* op0 = O + (size_t)(b * SS + i0 + r_q) * DD + h * DHH;
    float* op1 = op0 + 8 * DD;
    #pragma unroll
    for (int nt = 0; nt < 8; nt++) {
        float v0 = o[nt][0] * inv0, v1 = o[nt][1] * inv0;
        float v2 = o[nt][2] * inv1, v3 = o[nt][3] * inv1;
        *(float2*)(op0 + nt * 8 + 2 * tig) = make_float2(v0, v1);
        *(float2*)(op1 + nt * 8 + 2 * tig) = make_float2(v2, v3);
        psum += v0 + v1 + v2 + v3;
        psq  += v0 * v0 + v1 * v1 + v2 * v2 + v3 * v3;
    }
    double ds = (double)psum, dq = (double)psq;
    #pragma unroll
    for (int off = 16; off > 0; off >>= 1) {
        ds += __shfl_xor_sync(0xffffffffu, ds, off);
        dq += __shfl_xor_sync(0xffffffffu, dq, off);
    }
    __shared__ double wsum[4], wsq[4];
    if (lane == 0) { wsum[warp] = ds; wsq[warp] = dq; }
    __syncthreads();
    if (tid == 0) {
        double ts = wsum[0] + wsum[1] + wsum[2] + wsum[3];
        double tq = wsq[0] + wsq[1] + wsq[2] + wsq[3];
        part[tile * 2 + 0] = ts;
        part[tile * 2 + 1] = tq;
    }
}

// ---------------------------------------------------------------------------
extern "C" void kernel_launch(void* const* d_in, const int* in_sizes, int n_in,
                              void* d_out, int out_size) {
    const float* x   = (const float*)d_in[0];
    const float* Wq  = (const float*)d_in[1];
    const float* bq  = (const float*)d_in[2];
    const float* Wk  = (const float*)d_in[3];
    const float* bk  = (const float*)d_in[4];
    const float* Wv  = (const float*)d_in[5];
    const float* bv  = (const float*)d_in[6];
    const float* Wo  = (const float*)d_in[7];
    const float* bo  = (const float*)d_in[8];
    const float* lq1 = (const float*)d_in[9];
    const float* lk1 = (const float*)d_in[10];
    const float* lq2 = (const float*)d_in[11];
    const float* lk2 = (const float*)d_in[12];
    const float* gnw = (const float*)d_in[13];
    const float* gnb = (const float*)d_in[14];
    float* y = (float*)d_out;

    float *Qp, *Kp, *Vp, *AOp, *Xrp, *Wrp, *lamp;
    double* partp;
    cudaGetSymbolAddress((void**)&Qp,    g_Q);
    cudaGetSymbolAddress((void**)&Kp,    g_K);
    cudaGetSymbolAddress((void**)&Vp,    g_V);
    cudaGetSymbolAddress((void**)&AOp,   g_AO);
    cudaGetSymbolAddress((void**)&Xrp,   g_Xr);
    cudaGetSymbolAddress((void**)&Wrp,   g_Wr);
    cudaGetSymbolAddress((void**)&lamp,  g_lam);
    cudaGetSymbolAddress((void**)&partp, g_part);

    float* Wrq = Wrp;
    float* Wrk = Wrp + (size_t)DD * DD;
    float* Wrv = Wrp + (size_t)2 * DD * DD;
    float* Wro = Wrp + (size_t)3 * DD * DD;

    static int attr_set = 0;
    if (!attr_set) {
        cudaFuncSetAttribute(flash_tf32, cudaFuncAttributeMaxDynamicSharedMemorySize,
                             FLASH_SMEM);
        attr_set = 1;
    }

    // pre-round x + 4 weights + lambda, one launch
    tf32_round_all<<<NR_BLOCKS + 1, 256>>>(x, Xrp, Wq, Wk, Wv, Wo, Wrp,
                                           lq1, lk1, lq2, lk2, lamp);

    gemm_qkv<<<dim3(24, 32), 256>>>(Xrp, Wrq, Wrk, Wrv, bq, bk, bv, Qp, Kp, Vp);

    flash_tf32<<<FLASH_TILES, 128, FLASH_SMEM>>>(Qp, Kp, Vp, lamp, AOp, partp);

    gemm_o<<<dim3(8, 32), 256>>>(AOp, Wro, bo, y, partp, gnw, gnb);
}